// round 9
// baseline (speedup 1.0000x reference)
#include <cuda_runtime.h>
#include <cuda_fp16.h>

#define N_NODES  100000
#define N_EDGES  3200000
#define N_GRAPHS 512
#define F1 35
#define F2 128
#define KDIM 70
#define RPAD 48                         // fp16 row padded to 48 halves = 96B = 3 sectors
#define NB ((N_NODES + 1023) / 1024)    // 98 scan blocks
#define CNT_BLK (N_EDGES / 4 / 256)     // 3125 (4 edges/thread)
#define CONV_BLK (N_NODES * 24 / 256)   // 9375

// ---------------- device scratch (zero-initialized at load) ----------------
__device__ int    d_cnt[N_NODES];        // re-zeroed by scan_scatter each call
__device__ int    d_off[N_NODES + 1];
__device__ int    d_cur[N_NODES];
__device__ int    d_bsum[NB];
__device__ int    d_csr_src[N_EDGES];
__device__ float  d_agg[N_NODES * F1];
__device__ __half d_xh[N_NODES * RPAD];  // padded fp16 rows; pads stay 0 forever
__device__ int    d_gmax[N_GRAPHS * F2];

#define FMA_F32X2(d, a, b, c) \
    asm("fma.rn.f32x2 %0, %1, %2, %3;" : "=l"(d) : "l"(a), "l"(b), "l"(c))
#define PACK_F32X2(out, lo, hi) \
    asm("mov.b64 %0, {%1, %2};" : "=l"(out) : "f"(lo), "f"(hi))
#define UNPACK_F32X2(lo, hi, in) \
    asm("mov.b64 {%0, %1}, %2;" : "=f"(lo), "=f"(hi) : "l"(in))

__device__ __forceinline__ int fkey(float f) {
    int i = __float_as_int(f);
    return i >= 0 ? i : (i ^ 0x7FFFFFFF);
}

// m16n8k16 fp16 MMA, fp32 accumulate (row-major A, col-major B)
__device__ __forceinline__ void mma16816(float* d, const unsigned* a, const unsigned* b) {
    asm volatile(
        "mma.sync.aligned.m16n8k16.row.col.f32.f16.f16.f32 "
        "{%0,%1,%2,%3}, {%4,%5,%6,%7}, {%8,%9}, {%0,%1,%2,%3};\n"
        : "+f"(d[0]), "+f"(d[1]), "+f"(d[2]), "+f"(d[3])
        : "r"(a[0]), "r"(a[1]), "r"(a[2]), "r"(a[3]), "r"(b[0]), "r"(b[1]));
}

// ---------------- K1: degree count (4 edges/thread) + conv(x -> fp16 rows), fused ----------------
__global__ void pre_kernel(const float* __restrict__ x, const int* __restrict__ dst) {
    int b = blockIdx.x, t = threadIdx.x;
    if (b < CNT_BLK) {
        int i = b * 256 + t;
        int4 d4 = __ldg(&((const int4*)dst)[i]);
        atomicAdd(&d_cnt[d4.x], 1);
        atomicAdd(&d_cnt[d4.y], 1);
        atomicAdd(&d_cnt[d4.z], 1);
        atomicAdd(&d_cnt[d4.w], 1);
    } else {
        int i = (b - CNT_BLK) * 256 + t;           // half2 slot
        if (i < N_NODES * 24) {
            int n = i / 24, c = i - n * 24;
            int f0 = 2 * c, f1 = 2 * c + 1;
            float v0 = (f0 < F1) ? x[n * F1 + f0] : 0.f;
            float v1 = (f1 < F1) ? x[n * F1 + f1] : 0.f;
            ((__half2*)d_xh)[n * 24 + c] = __floats2half2_rn(v0, v1);
        }
    }
}

// ---------------- scan part sums (+ d_gmax reset) ----------------
__global__ __launch_bounds__(1024) void scan_part_kernel() {
    __shared__ int ws[32];
    int b = blockIdx.x, t = threadIdx.x;
    int i = b * 1024 + t;
    if (i < N_GRAPHS * F2) d_gmax[i] = (int)0x807FFFFFu;   // fkey(-inf)
    int v = (i < N_NODES) ? d_cnt[i] : 0;
    int s = v;
#pragma unroll
    for (int o = 16; o > 0; o >>= 1) s += __shfl_down_sync(0xffffffffu, s, o);
    if ((t & 31) == 0) ws[t >> 5] = s;
    __syncthreads();
    if (t < 32) {
        int x = ws[t];
#pragma unroll
        for (int o = 16; o > 0; o >>= 1) x += __shfl_down_sync(0xffffffffu, x, o);
        if (t == 0) d_bsum[b] = x;
    }
}

// ---------------- scan scatter (inline top prefix; re-zeroes d_cnt) ----------------
__global__ __launch_bounds__(1024) void scan_scatter_kernel() {
    __shared__ int ws[32];
    __shared__ int sc[4];
    int b = blockIdx.x, t = threadIdx.x;
    int lane = t & 31, wid = t >> 5;

    if (t < 128) {
        int pv = (t < NB && t < b) ? d_bsum[t] : 0;
#pragma unroll
        for (int o = 16; o > 0; o >>= 1) pv += __shfl_down_sync(0xffffffffu, pv, o);
        if (lane == 0) sc[wid] = pv;
    }

    int i = b * 1024 + t;
    int v = (i < N_NODES) ? d_cnt[i] : 0;
    int incl = v;
#pragma unroll
    for (int o = 1; o < 32; o <<= 1) {
        int x = __shfl_up_sync(0xffffffffu, incl, o);
        if (lane >= o) incl += x;
    }
    if (lane == 31) ws[wid] = incl;
    __syncthreads();
    int carry = sc[0] + sc[1] + sc[2] + sc[3];
    if (t < 32) {
        int x = ws[t], xi = x;
#pragma unroll
        for (int o = 1; o < 32; o <<= 1) {
            int y = __shfl_up_sync(0xffffffffu, xi, o);
            if (lane >= o) xi += y;
        }
        ws[t] = xi - x;
    }
    __syncthreads();
    int ex = carry + ws[wid] + (incl - v);
    if (i < N_NODES) {
        d_off[i] = ex;
        d_cur[i] = ex;
        d_cnt[i] = 0;
        if (i == N_NODES - 1) d_off[N_NODES] = ex + v;
    }
}

// ---------------- CSR fill: 4 edges/thread ----------------
__global__ void fill_kernel(const int* __restrict__ src, const int* __restrict__ dst) {
    int i = blockIdx.x * blockDim.x + threadIdx.x;
    if (i >= N_EDGES / 4) return;
    int4 s4 = __ldg(&((const int4*)src)[i]);
    int4 d4 = __ldg(&((const int4*)dst)[i]);
    int p0 = atomicAdd(&d_cur[d4.x], 1);
    int p1 = atomicAdd(&d_cur[d4.y], 1);
    int p2 = atomicAdd(&d_cur[d4.z], 1);
    int p3 = atomicAdd(&d_cur[d4.w], 1);
    d_csr_src[p0] = s4.x;
    d_csr_src[p1] = s4.y;
    d_csr_src[p2] = s4.z;
    d_csr_src[p3] = s4.w;
}

// ---------------- mean aggregation: warp/node, register-staged indices ----------------
// One coalesced LDG loads 32 edge indices into the warp; feature-load addresses
// come from shuffles (no memory dependency) so all 7 inner iterations' LDG.128
// issue back-to-back (MLP ~7/lane instead of 1).
__global__ __launch_bounds__(256) void agg_kernel() {
    int w = (blockIdx.x * blockDim.x + threadIdx.x) >> 5;
    int lane = threadIdx.x & 31;
    if (w >= N_NODES) return;
    int g = lane / 6;            // edge group 0..4 (lanes 30,31 inactive)
    int p = lane - g * 6;        // 16B slice -> features 8p..8p+7
    bool active = g < 5;
    int beg = d_off[w], end = d_off[w + 1];
    int deg = end - beg;

    float acc[8];
#pragma unroll
    for (int i = 0; i < 8; i++) acc[i] = 0.f;

    const uint4* __restrict__ xh4 = (const uint4*)d_xh;
    for (int b0 = 0; b0 < deg; b0 += 32) {
        int nb = min(32, deg - b0);
        int idxv = (lane < nb) ? __ldg(&d_csr_src[beg + b0 + lane]) : 0;
#pragma unroll
        for (int it = 0; it < 7; it++) {
            int e = it * 5 + g;
            int s = __shfl_sync(0xffffffffu, idxv, e & 31);
            uint4 v = make_uint4(0u, 0u, 0u, 0u);
            if (active && e < nb) v = __ldg(&xh4[(long)s * 6 + p]);
            float2 f;
            f = __half22float2(*(__half2*)&v.x); acc[0] += f.x; acc[1] += f.y;
            f = __half22float2(*(__half2*)&v.y); acc[2] += f.x; acc[3] += f.y;
            f = __half22float2(*(__half2*)&v.z); acc[4] += f.x; acc[5] += f.y;
            f = __half22float2(*(__half2*)&v.w); acc[6] += f.x; acc[7] += f.y;
        }
    }
    // reduce the 5 edge groups (lanes p, p+6, p+12, p+18, p+24)
#pragma unroll
    for (int i = 0; i < 8; i++) {
        float t1 = __shfl_sync(0xffffffffu, acc[i], lane + 6);
        float t2 = __shfl_sync(0xffffffffu, acc[i], lane + 12);
        float t3 = __shfl_sync(0xffffffffu, acc[i], lane + 18);
        float t4 = __shfl_sync(0xffffffffu, acc[i], lane + 24);
        acc[i] += t1 + t2 + t3 + t4;
    }
    float inv = 1.0f / fmaxf((float)deg, 1.0f);
    if (lane < 6) {
#pragma unroll
        for (int i = 0; i < 8; i++) {
            int f = lane * 8 + i;
            if (f < F1) d_agg[(long)w * F1 + f] = acc[i] * inv;
        }
    }
}

// ---------------- lin1: fp32 FFMA2, out = relu([agg|x] @ W1 + b1) -> fp16 h1 rows ----------------
__global__ __launch_bounds__(256) void lin1_kernel(
    const float* __restrict__ xin, const float* __restrict__ Wl,
    const float* __restrict__ bl, const float* __restrict__ Wr)
{
    __shared__ __align__(16) float sAT[KDIM][36];
    __shared__ float sW[KDIM * F1];
    __shared__ float sbl[F1];

    const int tid = threadIdx.x;
    const int jt = tid & 31;
    const int mt = tid >> 5;
    const int base_n = blockIdx.x * 32;

    for (int idx = tid; idx < KDIM * F1; idx += 256) {
        int k = idx / F1, j = idx - k * F1;
        sW[idx] = (k < F1) ? Wl[k * F1 + j] : Wr[(k - F1) * F1 + j];
    }
    if (tid < F1) sbl[tid] = bl[tid];
    for (int idx = tid; idx < 32 * F1; idx += 256) {
        int m = idx & 31, k = idx >> 5;
        long n = base_n + m;
        sAT[k][m]      = d_agg[n * F1 + k];
        sAT[k + F1][m] = xin[n * F1 + k];
    }
    __syncthreads();

    unsigned long long acc2[2][2];
#pragma unroll
    for (int p = 0; p < 2; p++)
#pragma unroll
        for (int c = 0; c < 2; c++) acc2[p][c] = 0ULL;

#pragma unroll 2
    for (int k = 0; k < KDIM; k++) {
        float4 a4 = *(const float4*)&sAT[k][mt * 4];
        unsigned long long a01, a23;
        PACK_F32X2(a01, a4.x, a4.y);
        PACK_F32X2(a23, a4.z, a4.w);
#pragma unroll
        for (int c = 0; c < 2; c++) {
            int j = jt + 32 * c;
            float w = (j < F1) ? sW[k * F1 + j] : 0.f;
            unsigned long long ww;
            PACK_F32X2(ww, w, w);
            FMA_F32X2(acc2[0][c], a01, ww, acc2[0][c]);
            FMA_F32X2(acc2[1][c], a23, ww, acc2[1][c]);
        }
    }

    const int n0 = base_n + mt * 4;
    float v[4];
#pragma unroll
    for (int c = 0; c < 2; c++) {
        int j = jt + 32 * c;
        if (j < F1) {
            UNPACK_F32X2(v[0], v[1], acc2[0][c]);
            UNPACK_F32X2(v[2], v[3], acc2[1][c]);
#pragma unroll
            for (int r = 0; r < 4; r++) {
                float o = fmaxf(v[r] + sbl[j], 0.f);
                d_xh[(long)(n0 + r) * RPAD + j] = __float2half(o);
            }
        }
    }
}

// ---------------- lin2 + max-pool: HMMA m16n8k16, 64 nodes/block ----------------
__global__ __launch_bounds__(256) void mma_pool_kernel(
    const float* __restrict__ Wl, const float* __restrict__ bl,
    const float* __restrict__ Wr, const int* __restrict__ batch)
{
    __shared__ __align__(16) __half sA[64 * 88];
    __shared__ __align__(16) __half sB[128 * 88];
    __shared__ float sbl[F2];
    __shared__ int   sgm[F2];

    const int tid = threadIdx.x;
    const int w = tid >> 5;
    const int lane = tid & 31;
    const int gid = lane >> 2;
    const int tig = lane & 3;
    const int base = blockIdx.x * 64;

    for (int idx = tid; idx < 64 * 80; idx += 256) {
        int m = idx / 80, k = idx - (idx / 80) * 80;
        long n = base + m;
        __half v = __ushort_as_half((unsigned short)0);
        if (n < N_NODES) {
            if (k < F1) v = __float2half(d_agg[n * F1 + k]);
            else if (k < KDIM) v = d_xh[n * RPAD + (k - F1)];
        }
        sA[m * 88 + k] = v;
    }
    for (int idx = tid; idx < 80 * F2; idx += 256) {
        int k = idx >> 7, n = idx & 127;
        float v = 0.f;
        if (k < F1) v = Wl[k * F2 + n];
        else if (k < KDIM) v = Wr[(k - F1) * F2 + n];
        sB[n * 88 + k] = __float2half(v);
    }
    if (tid < F2) { sbl[tid] = bl[tid]; sgm[tid] = (int)0x80000000; }
    __syncthreads();

    const int wm = w & 3;
    const int wn = (w >> 2) * 8;
    float acc[8][4];
#pragma unroll
    for (int nt = 0; nt < 8; nt++)
#pragma unroll
        for (int c = 0; c < 4; c++) acc[nt][c] = 0.f;

#pragma unroll
    for (int kc = 0; kc < 5; kc++) {
        const int k0 = kc * 16;
        unsigned a[4];
        const int ra = (wm * 16 + gid) * 88 + k0 + tig * 2;
        a[0] = *(const unsigned*)&sA[ra];
        a[1] = *(const unsigned*)&sA[ra + 8 * 88];
        a[2] = *(const unsigned*)&sA[ra + 8];
        a[3] = *(const unsigned*)&sA[ra + 8 * 88 + 8];
#pragma unroll
        for (int nt = 0; nt < 8; nt++) {
            unsigned b[2];
            const int rb = ((wn + nt) * 8 + gid) * 88 + k0 + tig * 2;
            b[0] = *(const unsigned*)&sB[rb];
            b[1] = *(const unsigned*)&sB[rb + 8];
            mma16816(acc[nt], a, b);
        }
    }

    const int r0 = base + wm * 16 + gid;
    const int r1 = r0 + 8;
    const bool full = (base + 63 < N_NODES);
    const int gfirst = batch[base];
    const bool single = full && (gfirst == batch[base + 63]);

    if (single) {
#pragma unroll
        for (int nt = 0; nt < 8; nt++) {
            int c0 = (wn + nt) * 8 + tig * 2;
            int k0v = max(fkey(acc[nt][0] + sbl[c0]),     fkey(acc[nt][2] + sbl[c0]));
            int k1v = max(fkey(acc[nt][1] + sbl[c0 + 1]), fkey(acc[nt][3] + sbl[c0 + 1]));
            atomicMax(&sgm[c0], k0v);
            atomicMax(&sgm[c0 + 1], k1v);
        }
        __syncthreads();
        if (tid < F2) atomicMax(&d_gmax[gfirst * F2 + tid], sgm[tid]);
    } else {
        int b0 = (r0 < N_NODES) ? batch[r0] : -1;
        int b1 = (r1 < N_NODES) ? batch[r1] : -1;
#pragma unroll
        for (int nt = 0; nt < 8; nt++) {
            int c0 = (wn + nt) * 8 + tig * 2;
            if (b0 >= 0) {
                atomicMax(&d_gmax[b0 * F2 + c0],     fkey(acc[nt][0] + sbl[c0]));
                atomicMax(&d_gmax[b0 * F2 + c0 + 1], fkey(acc[nt][1] + sbl[c0 + 1]));
            }
            if (b1 >= 0) {
                atomicMax(&d_gmax[b1 * F2 + c0],     fkey(acc[nt][2] + sbl[c0]));
                atomicMax(&d_gmax[b1 * F2 + c0 + 1], fkey(acc[nt][3] + sbl[c0 + 1]));
            }
        }
    }
}

// ---------------- FC head ----------------
__global__ __launch_bounds__(128) void head_kernel(
    const float* __restrict__ Wg1, const float* __restrict__ bg1,
    const float* __restrict__ Wg2, const float* __restrict__ bg2,
    const float* __restrict__ Wo,  const float* __restrict__ bo,
    float* __restrict__ out)
{
    int g = blockIdx.x, j = threadIdx.x;
    __shared__ float r0[F2], r1[F2];
    __shared__ float wred[4];
    int key = d_gmax[g * F2 + j];
    key = key >= 0 ? key : (key ^ 0x7FFFFFFF);
    r0[j] = __int_as_float(key);
    __syncthreads();
    float acc = bg1[j];
#pragma unroll 8
    for (int k = 0; k < F2; k++) acc += r0[k] * Wg1[k * F2 + j];
    r1[j] = fmaxf(acc, 0.f);
    __syncthreads();
    acc = bg2[j];
#pragma unroll 8
    for (int k = 0; k < F2; k++) acc += r1[k] * Wg2[k * F2 + j];
    float v = fmaxf(acc, 0.f) * Wo[j];
#pragma unroll
    for (int s = 16; s > 0; s >>= 1) v += __shfl_down_sync(0xffffffffu, v, s);
    if ((j & 31) == 0) wred[j >> 5] = v;
    __syncthreads();
    if (j == 0) out[g] = wred[0] + wred[1] + wred[2] + wred[3] + bo[0];
}

// ---------------- launcher (9 kernels) ----------------
extern "C" void kernel_launch(void* const* d_in, const int* in_sizes, int n_in,
                              void* d_out, int out_size) {
    const float* x    = (const float*)d_in[0];
    const int*   ei   = (const int*)d_in[1];
    const int*   bat  = (const int*)d_in[2];
    const float* Wl1  = (const float*)d_in[3];
    const float* bl1  = (const float*)d_in[4];
    const float* Wr1  = (const float*)d_in[5];
    const float* Wl2  = (const float*)d_in[6];
    const float* bl2  = (const float*)d_in[7];
    const float* Wr2  = (const float*)d_in[8];
    const float* Wg1  = (const float*)d_in[9];
    const float* bg1  = (const float*)d_in[10];
    const float* Wg2  = (const float*)d_in[11];
    const float* bg2  = (const float*)d_in[12];
    const float* Wo   = (const float*)d_in[13];
    const float* bo   = (const float*)d_in[14];
    float* out = (float*)d_out;

    const int* src = ei;
    const int* dst = ei + N_EDGES;

    pre_kernel<<<CNT_BLK + CONV_BLK, 256>>>(x, dst);
    scan_part_kernel<<<NB, 1024>>>();
    scan_scatter_kernel<<<NB, 1024>>>();
    fill_kernel<<<(N_EDGES / 4 + 255) / 256, 256>>>(src, dst);

    agg_kernel<<<(N_NODES * 32 + 255) / 256, 256>>>();                  // agg(x)
    lin1_kernel<<<N_NODES / 32, 256>>>(x, Wl1, bl1, Wr1);               // -> fp16 h1

    agg_kernel<<<(N_NODES * 32 + 255) / 256, 256>>>();                  // agg(h1)
    mma_pool_kernel<<<(N_NODES + 63) / 64, 256>>>(Wl2, bl2, Wr2, bat);  // lin2 + pool

    head_kernel<<<N_GRAPHS, F2>>>(Wg1, bg1, Wg2, bg2, Wo, bo, out);
}

// round 10
// speedup vs baseline: 1.0874x; 1.0874x over previous
#include <cuda_runtime.h>
#include <cuda_fp16.h>

#define N_NODES  100000
#define N_EDGES  3200000
#define N_GRAPHS 512
#define F1 35
#define F2 128
#define KDIM 70
#define RPAD 48                         // fp16 row padded to 48 halves = 96B = 3 sectors
#define APAD 48                         // agg fp16 row stride (halves)
#define NB ((N_NODES + 1023) / 1024)    // 98 scan blocks
#define CNT_BLK (N_EDGES / 4 / 256)     // 3125 (4 edges/thread)
#define CONV_BLK (N_NODES * 24 / 256)   // 9375

// ---------------- device scratch (zero-initialized at load) ----------------
__device__ int    d_cnt[N_NODES];        // re-zeroed by scan each call
__device__ int    d_off[N_NODES + 1];
__device__ int    d_cur[N_NODES];
__device__ int    d_bsum[NB];
__device__ int    g_ctr_a, g_ctr_b;      // grid barrier counters (reset each call)
__device__ int    d_csr_src[N_EDGES];
__device__ __half d_a2[N_NODES * APAD];  // fp16 agg rows; pads stay 0
__device__ __half d_xh[N_NODES * RPAD];  // padded fp16 feature rows; pads stay 0
__device__ int    d_gmax[N_GRAPHS * F2];

#define FMA_F32X2(d, a, b, c) \
    asm("fma.rn.f32x2 %0, %1, %2, %3;" : "=l"(d) : "l"(a), "l"(b), "l"(c))
#define PACK_F32X2(out, lo, hi) \
    asm("mov.b64 %0, {%1, %2};" : "=l"(out) : "f"(lo), "f"(hi))
#define UNPACK_F32X2(lo, hi, in) \
    asm("mov.b64 {%0, %1}, %2;" : "=f"(lo), "=f"(hi) : "l"(in))

__device__ __forceinline__ int fkey(float f) {
    int i = __float_as_int(f);
    return i >= 0 ? i : (i ^ 0x7FFFFFFF);
}

// m16n8k16 fp16 MMA, fp32 accumulate (row-major A, col-major B)
__device__ __forceinline__ void mma16816(float* d, const unsigned* a, const unsigned* b) {
    asm volatile(
        "mma.sync.aligned.m16n8k16.row.col.f32.f16.f16.f32 "
        "{%0,%1,%2,%3}, {%4,%5,%6,%7}, {%8,%9}, {%0,%1,%2,%3};\n"
        : "+f"(d[0]), "+f"(d[1]), "+f"(d[2]), "+f"(d[3])
        : "r"(a[0]), "r"(a[1]), "r"(a[2]), "r"(a[3]), "r"(b[0]), "r"(b[1]));
}

// ---------------- K0: degree count (4 edges/thread) + conv(x -> fp16 rows), fused ----------------
__global__ void pre_kernel(const float* __restrict__ x, const int* __restrict__ dst) {
    int b = blockIdx.x, t = threadIdx.x;
    if (b < CNT_BLK) {
        int i = b * 256 + t;
        int4 d4 = __ldg(&((const int4*)dst)[i]);
        atomicAdd(&d_cnt[d4.x], 1);
        atomicAdd(&d_cnt[d4.y], 1);
        atomicAdd(&d_cnt[d4.z], 1);
        atomicAdd(&d_cnt[d4.w], 1);
    } else {
        int i = (b - CNT_BLK) * 256 + t;           // half2 slot
        if (i < N_NODES * 24) {
            int n = i / 24, c = i - n * 24;
            int f0 = 2 * c, f1 = 2 * c + 1;
            float v0 = (f0 < F1) ? x[n * F1 + f0] : 0.f;
            float v1 = (f1 < F1) ? x[n * F1 + f1] : 0.f;
            ((__half2*)d_xh)[n * 24 + c] = __floats2half2_rn(v0, v1);
        }
    }
}

// ---------------- K1: fused exclusive scan (grid barrier), + gmax reset, + cnt reset ----------------
__global__ __launch_bounds__(1024) void scan_kernel() {
    __shared__ int ws[32];
    __shared__ int sc[4];
    const int b = blockIdx.x, t = threadIdx.x;
    const int lane = t & 31, wid = t >> 5;
    const int i = b * 1024 + t;

    if (i < N_GRAPHS * F2) d_gmax[i] = (int)0x807FFFFFu;   // fkey(-inf)

    const int v = (i < N_NODES) ? d_cnt[i] : 0;

    // ---- phase A: block sum -> d_bsum[b] ----
    int s = v;
#pragma unroll
    for (int o = 16; o > 0; o >>= 1) s += __shfl_down_sync(0xffffffffu, s, o);
    if (lane == 0) ws[wid] = s;
    __syncthreads();
    if (t < 32) {
        int xv = ws[t];
#pragma unroll
        for (int o = 16; o > 0; o >>= 1) xv += __shfl_down_sync(0xffffffffu, xv, o);
        if (t == 0) {
            d_bsum[b] = xv;
            __threadfence();
            atomicAdd(&g_ctr_a, 1);
        }
    }
    // ---- grid barrier: wait for all 98 block sums ----
    if (t == 0) { while (atomicAdd(&g_ctr_a, 0) < NB) { } }
    __syncthreads();
    __threadfence();

    // ---- phase B: inline prefix over block sums (carry for block b) ----
    if (t < 128) {
        int pv = (t < NB && t < b) ? d_bsum[t] : 0;
#pragma unroll
        for (int o = 16; o > 0; o >>= 1) pv += __shfl_down_sync(0xffffffffu, pv, o);
        if (lane == 0) sc[wid] = pv;
    }
    int incl = v;
#pragma unroll
    for (int o = 1; o < 32; o <<= 1) {
        int xv = __shfl_up_sync(0xffffffffu, incl, o);
        if (lane >= o) incl += xv;
    }
    if (lane == 31) ws[wid] = incl;
    __syncthreads();
    const int carry = sc[0] + sc[1] + sc[2] + sc[3];
    if (t < 32) {
        int xv = ws[t], xi = xv;
#pragma unroll
        for (int o = 1; o < 32; o <<= 1) {
            int y = __shfl_up_sync(0xffffffffu, xi, o);
            if (lane >= o) xi += y;
        }
        ws[t] = xi - xv;
    }
    __syncthreads();
    const int ex = carry + ws[wid] + (incl - v);
    if (i < N_NODES) {
        d_off[i] = ex;
        d_cur[i] = ex;
        d_cnt[i] = 0;                      // graph-replay invariant
        if (i == N_NODES - 1) d_off[N_NODES] = ex + v;
    }
    // ---- release: last block resets both counters for the next call ----
    __syncthreads();
    if (t == 0) {
        int r = atomicAdd(&g_ctr_b, 1);
        if (r == NB - 1) { atomicExch(&g_ctr_a, 0); atomicExch(&g_ctr_b, 0); }
    }
}

// ---------------- K2: CSR fill, 4 edges/thread ----------------
__global__ void fill_kernel(const int* __restrict__ src, const int* __restrict__ dst) {
    int i = blockIdx.x * blockDim.x + threadIdx.x;
    if (i >= N_EDGES / 4) return;
    int4 s4 = __ldg(&((const int4*)src)[i]);
    int4 d4 = __ldg(&((const int4*)dst)[i]);
    int p0 = atomicAdd(&d_cur[d4.x], 1);
    int p1 = atomicAdd(&d_cur[d4.y], 1);
    int p2 = atomicAdd(&d_cur[d4.z], 1);
    int p3 = atomicAdd(&d_cur[d4.w], 1);
    d_csr_src[p0] = s4.x;
    d_csr_src[p1] = s4.y;
    d_csr_src[p2] = s4.z;
    d_csr_src[p3] = s4.w;
}

// ---------------- K3: mean aggregation (warp/node, 5 edges/iter) -> fp16 rows ----------------
__global__ __launch_bounds__(256) void agg_kernel() {
    int w = (blockIdx.x * blockDim.x + threadIdx.x) >> 5;
    int lane = threadIdx.x & 31;
    if (w >= N_NODES) return;
    int g = lane / 6;            // edge group 0..4 (lanes 30,31 inactive)
    int p = lane - g * 6;        // 16B slice -> features 8p..8p+7
    bool active = g < 5;
    int beg = d_off[w], end = d_off[w + 1];

    float acc[8];
#pragma unroll
    for (int i = 0; i < 8; i++) acc[i] = 0.f;

    const uint4* __restrict__ xh4 = (const uint4*)d_xh;
#pragma unroll 4
    for (int e0 = beg; e0 < end; e0 += 5) {
        int e = e0 + g;
        if (active && e < end) {
            int s = d_csr_src[e];
            uint4 v = __ldg(&xh4[(long)s * 6 + p]);
            float2 f;
            f = __half22float2(*(__half2*)&v.x); acc[0] += f.x; acc[1] += f.y;
            f = __half22float2(*(__half2*)&v.y); acc[2] += f.x; acc[3] += f.y;
            f = __half22float2(*(__half2*)&v.z); acc[4] += f.x; acc[5] += f.y;
            f = __half22float2(*(__half2*)&v.w); acc[6] += f.x; acc[7] += f.y;
        }
    }
#pragma unroll
    for (int i = 0; i < 8; i++) {
        float t1 = __shfl_sync(0xffffffffu, acc[i], lane + 6);
        float t2 = __shfl_sync(0xffffffffu, acc[i], lane + 12);
        float t3 = __shfl_sync(0xffffffffu, acc[i], lane + 18);
        float t4 = __shfl_sync(0xffffffffu, acc[i], lane + 24);
        acc[i] += t1 + t2 + t3 + t4;
    }
    float inv = 1.0f / fmaxf((float)(end - beg), 1.0f);
    if (lane < 6) {
        __half2 h0 = __floats2half2_rn(acc[0] * inv, acc[1] * inv);
        __half2 h1 = __floats2half2_rn(acc[2] * inv, acc[3] * inv);
        __half2 h2 = __floats2half2_rn(acc[4] * inv, acc[5] * inv);
        __half2 h3 = __floats2half2_rn(acc[6] * inv, acc[7] * inv);
        uint4 u;
        u.x = *(unsigned*)&h0; u.y = *(unsigned*)&h1;
        u.z = *(unsigned*)&h2; u.w = *(unsigned*)&h3;
        ((uint4*)(d_a2 + (long)w * APAD))[lane] = u;   // pads (35..47) rewritten as 0
    }
}

// ---------------- K4: lin1 fp32 FFMA2, out = relu([agg|x] @ W1 + b1) -> fp16 h1 rows ----------------
__global__ __launch_bounds__(256) void lin1_kernel(
    const float* __restrict__ xin, const float* __restrict__ Wl,
    const float* __restrict__ bl, const float* __restrict__ Wr)
{
    __shared__ __align__(16) float sAT[KDIM][36];
    __shared__ float sW[KDIM * F1];
    __shared__ float sbl[F1];

    const int tid = threadIdx.x;
    const int jt = tid & 31;
    const int mt = tid >> 5;
    const int base_n = blockIdx.x * 32;

    for (int idx = tid; idx < KDIM * F1; idx += 256) {
        int k = idx / F1, j = idx - k * F1;
        sW[idx] = (k < F1) ? Wl[k * F1 + j] : Wr[(k - F1) * F1 + j];
    }
    if (tid < F1) sbl[tid] = bl[tid];
    for (int idx = tid; idx < 32 * F1; idx += 256) {
        int m = idx & 31, k = idx >> 5;
        long n = base_n + m;
        sAT[k][m]      = __half2float(d_a2[n * APAD + k]);
        sAT[k + F1][m] = xin[n * F1 + k];
    }
    __syncthreads();

    unsigned long long acc2[2][2];
#pragma unroll
    for (int p = 0; p < 2; p++)
#pragma unroll
        for (int c = 0; c < 2; c++) acc2[p][c] = 0ULL;

#pragma unroll 2
    for (int k = 0; k < KDIM; k++) {
        float4 a4 = *(const float4*)&sAT[k][mt * 4];
        unsigned long long a01, a23;
        PACK_F32X2(a01, a4.x, a4.y);
        PACK_F32X2(a23, a4.z, a4.w);
#pragma unroll
        for (int c = 0; c < 2; c++) {
            int j = jt + 32 * c;
            float w = (j < F1) ? sW[k * F1 + j] : 0.f;
            unsigned long long ww;
            PACK_F32X2(ww, w, w);
            FMA_F32X2(acc2[0][c], a01, ww, acc2[0][c]);
            FMA_F32X2(acc2[1][c], a23, ww, acc2[1][c]);
        }
    }

    const int n0 = base_n + mt * 4;
    float v[4];
#pragma unroll
    for (int c = 0; c < 2; c++) {
        int j = jt + 32 * c;
        if (j < F1) {
            UNPACK_F32X2(v[0], v[1], acc2[0][c]);
            UNPACK_F32X2(v[2], v[3], acc2[1][c]);
#pragma unroll
            for (int r = 0; r < 4; r++) {
                float o = fmaxf(v[r] + sbl[j], 0.f);
                d_xh[(long)(n0 + r) * RPAD + j] = __float2half(o);
            }
        }
    }
}

// ---------------- K6: lin2 + max-pool: HMMA m16n8k16, 64 nodes/block ----------------
__global__ __launch_bounds__(256) void mma_pool_kernel(
    const float* __restrict__ Wl, const float* __restrict__ bl,
    const float* __restrict__ Wr, const int* __restrict__ batch)
{
    __shared__ __align__(16) __half sA[64 * 88];
    __shared__ __align__(16) __half sB[128 * 88];
    __shared__ float sbl[F2];
    __shared__ int   sgm[F2];

    const int tid = threadIdx.x;
    const int w = tid >> 5;
    const int lane = tid & 31;
    const int gid = lane >> 2;
    const int tig = lane & 3;
    const int base = blockIdx.x * 64;

    for (int idx = tid; idx < 64 * 80; idx += 256) {
        int m = idx / 80, k = idx - (idx / 80) * 80;
        long n = base + m;
        __half v = __ushort_as_half((unsigned short)0);
        if (n < N_NODES) {
            if (k < F1) v = d_a2[n * APAD + k];
            else if (k < KDIM) v = d_xh[n * RPAD + (k - F1)];
        }
        sA[m * 88 + k] = v;
    }
    for (int idx = tid; idx < 80 * F2; idx += 256) {
        int k = idx >> 7, n = idx & 127;
        float v = 0.f;
        if (k < F1) v = Wl[k * F2 + n];
        else if (k < KDIM) v = Wr[(k - F1) * F2 + n];
        sB[n * 88 + k] = __float2half(v);
    }
    if (tid < F2) { sbl[tid] = bl[tid]; sgm[tid] = (int)0x80000000; }
    __syncthreads();

    const int wm = w & 3;
    const int wn = (w >> 2) * 8;
    float acc[8][4];
#pragma unroll
    for (int nt = 0; nt < 8; nt++)
#pragma unroll
        for (int c = 0; c < 4; c++) acc[nt][c] = 0.f;

#pragma unroll
    for (int kc = 0; kc < 5; kc++) {
        const int k0 = kc * 16;
        unsigned a[4];
        const int ra = (wm * 16 + gid) * 88 + k0 + tig * 2;
        a[0] = *(const unsigned*)&sA[ra];
        a[1] = *(const unsigned*)&sA[ra + 8 * 88];
        a[2] = *(const unsigned*)&sA[ra + 8];
        a[3] = *(const unsigned*)&sA[ra + 8 * 88 + 8];
#pragma unroll
        for (int nt = 0; nt < 8; nt++) {
            unsigned b[2];
            const int rb = ((wn + nt) * 8 + gid) * 88 + k0 + tig * 2;
            b[0] = *(const unsigned*)&sB[rb];
            b[1] = *(const unsigned*)&sB[rb + 8];
            mma16816(acc[nt], a, b);
        }
    }

    const int r0 = base + wm * 16 + gid;
    const int r1 = r0 + 8;
    const bool full = (base + 63 < N_NODES);
    const int gfirst = batch[base];
    const bool single = full && (gfirst == batch[base + 63]);

    if (single) {
#pragma unroll
        for (int nt = 0; nt < 8; nt++) {
            int c0 = (wn + nt) * 8 + tig * 2;
            int k0v = max(fkey(acc[nt][0] + sbl[c0]),     fkey(acc[nt][2] + sbl[c0]));
            int k1v = max(fkey(acc[nt][1] + sbl[c0 + 1]), fkey(acc[nt][3] + sbl[c0 + 1]));
            atomicMax(&sgm[c0], k0v);
            atomicMax(&sgm[c0 + 1], k1v);
        }
        __syncthreads();
        if (tid < F2) atomicMax(&d_gmax[gfirst * F2 + tid], sgm[tid]);
    } else {
        int b0 = (r0 < N_NODES) ? batch[r0] : -1;
        int b1 = (r1 < N_NODES) ? batch[r1] : -1;
#pragma unroll
        for (int nt = 0; nt < 8; nt++) {
            int c0 = (wn + nt) * 8 + tig * 2;
            if (b0 >= 0) {
                atomicMax(&d_gmax[b0 * F2 + c0],     fkey(acc[nt][0] + sbl[c0]));
                atomicMax(&d_gmax[b0 * F2 + c0 + 1], fkey(acc[nt][1] + sbl[c0 + 1]));
            }
            if (b1 >= 0) {
                atomicMax(&d_gmax[b1 * F2 + c0],     fkey(acc[nt][2] + sbl[c0]));
                atomicMax(&d_gmax[b1 * F2 + c0 + 1], fkey(acc[nt][3] + sbl[c0 + 1]));
            }
        }
    }
}

// ---------------- K7: FC head ----------------
__global__ __launch_bounds__(128) void head_kernel(
    const float* __restrict__ Wg1, const float* __restrict__ bg1,
    const float* __restrict__ Wg2, const float* __restrict__ bg2,
    const float* __restrict__ Wo,  const float* __restrict__ bo,
    float* __restrict__ out)
{
    int g = blockIdx.x, j = threadIdx.x;
    __shared__ float r0[F2], r1[F2];
    __shared__ float wred[4];
    int key = d_gmax[g * F2 + j];
    key = key >= 0 ? key : (key ^ 0x7FFFFFFF);
    r0[j] = __int_as_float(key);
    __syncthreads();
    float acc = bg1[j];
#pragma unroll 8
    for (int k = 0; k < F2; k++) acc += r0[k] * Wg1[k * F2 + j];
    r1[j] = fmaxf(acc, 0.f);
    __syncthreads();
    acc = bg2[j];
#pragma unroll 8
    for (int k = 0; k < F2; k++) acc += r1[k] * Wg2[k * F2 + j];
    float v = fmaxf(acc, 0.f) * Wo[j];
#pragma unroll
    for (int s = 16; s > 0; s >>= 1) v += __shfl_down_sync(0xffffffffu, v, s);
    if ((j & 31) == 0) wred[j >> 5] = v;
    __syncthreads();
    if (j == 0) out[g] = wred[0] + wred[1] + wred[2] + wred[3] + bo[0];
}

// ---------------- launcher (8 kernels; agg1 at capture index 3) ----------------
extern "C" void kernel_launch(void* const* d_in, const int* in_sizes, int n_in,
                              void* d_out, int out_size) {
    const float* x    = (const float*)d_in[0];
    const int*   ei   = (const int*)d_in[1];
    const int*   bat  = (const int*)d_in[2];
    const float* Wl1  = (const float*)d_in[3];
    const float* bl1  = (const float*)d_in[4];
    const float* Wr1  = (const float*)d_in[5];
    const float* Wl2  = (const float*)d_in[6];
    const float* bl2  = (const float*)d_in[7];
    const float* Wr2  = (const float*)d_in[8];
    const float* Wg1  = (const float*)d_in[9];
    const float* bg1  = (const float*)d_in[10];
    const float* Wg2  = (const float*)d_in[11];
    const float* bg2  = (const float*)d_in[12];
    const float* Wo   = (const float*)d_in[13];
    const float* bo   = (const float*)d_in[14];
    float* out = (float*)d_out;

    const int* src = ei;
    const int* dst = ei + N_EDGES;

    pre_kernel<<<CNT_BLK + CONV_BLK, 256>>>(x, dst);                    // 0
    scan_kernel<<<NB, 1024>>>();                                        // 1 (fused scan)
    fill_kernel<<<(N_EDGES / 4 + 255) / 256, 256>>>(src, dst);          // 2

    agg_kernel<<<(N_NODES * 32 + 255) / 256, 256>>>();                  // 3 <- profiled
    lin1_kernel<<<N_NODES / 32, 256>>>(x, Wl1, bl1, Wr1);               // 4

    agg_kernel<<<(N_NODES * 32 + 255) / 256, 256>>>();                  // 5
    mma_pool_kernel<<<(N_NODES + 63) / 64, 256>>>(Wl2, bl2, Wr2, bat);  // 6

    head_kernel<<<N_GRAPHS, F2>>>(Wg1, bg1, Wg2, bg2, Wo, bo, out);     // 7
}

// round 11
// speedup vs baseline: 1.1291x; 1.0384x over previous
#include <cuda_runtime.h>
#include <cuda_fp16.h>

#define N_NODES  100000
#define N_EDGES  3200000
#define N_GRAPHS 512
#define F1 35
#define F2 128
#define KDIM 70
#define RPAD 48                         // fp16 row padded to 48 halves = 96B = 3 sectors
#define APAD 48                         // agg fp16 row stride (halves)
#define NB ((N_NODES + 1023) / 1024)    // 98 scan blocks
#define CNT_BLK (N_EDGES / 4 / 256)     // 3125 (4 edges/thread)
#define CONV_BLK (N_NODES * 24 / 256)   // 9375

// ---------------- device scratch (zero-initialized at load) ----------------
__device__ int    d_cnt[N_NODES];        // re-zeroed by scan each call
__device__ int    d_off[N_NODES + 1];
__device__ int    d_cur[N_NODES];
__device__ int    d_bsum[NB];
__device__ int    g_ctr_a, g_ctr_b;      // grid barrier counters (reset each call)
__device__ int    d_csr_src[N_EDGES];
__device__ __half d_a2[N_NODES * APAD];  // fp16 agg rows; halves 40..47 stay 0 forever
__device__ __half d_xh[N_NODES * RPAD];  // padded fp16 feature rows; pads stay 0
__device__ int    d_gmax[N_GRAPHS * F2];

#define FMA_F32X2(d, a, b, c) \
    asm("fma.rn.f32x2 %0, %1, %2, %3;" : "=l"(d) : "l"(a), "l"(b), "l"(c))
#define PACK_F32X2(out, lo, hi) \
    asm("mov.b64 %0, {%1, %2};" : "=l"(out) : "f"(lo), "f"(hi))
#define UNPACK_F32X2(lo, hi, in) \
    asm("mov.b64 {%0, %1}, %2;" : "=f"(lo), "=f"(hi) : "l"(in))

__device__ __forceinline__ int fkey(float f) {
    int i = __float_as_int(f);
    return i >= 0 ? i : (i ^ 0x7FFFFFFF);
}

__device__ __forceinline__ unsigned hadd2u(unsigned a, unsigned b) {
    unsigned r;
    asm("add.rn.f16x2 %0, %1, %2;" : "=r"(r) : "r"(a), "r"(b));
    return r;
}

// m16n8k16 fp16 MMA, fp32 accumulate (row-major A, col-major B)
__device__ __forceinline__ void mma16816(float* d, const unsigned* a, const unsigned* b) {
    asm volatile(
        "mma.sync.aligned.m16n8k16.row.col.f32.f16.f16.f32 "
        "{%0,%1,%2,%3}, {%4,%5,%6,%7}, {%8,%9}, {%0,%1,%2,%3};\n"
        : "+f"(d[0]), "+f"(d[1]), "+f"(d[2]), "+f"(d[3])
        : "r"(a[0]), "r"(a[1]), "r"(a[2]), "r"(a[3]), "r"(b[0]), "r"(b[1]));
}

// ---------------- K0: degree count (4 edges/thread) + conv(x -> fp16 rows), fused ----------------
__global__ void pre_kernel(const float* __restrict__ x, const int* __restrict__ dst) {
    int b = blockIdx.x, t = threadIdx.x;
    if (b < CNT_BLK) {
        int i = b * 256 + t;
        int4 d4 = __ldg(&((const int4*)dst)[i]);
        atomicAdd(&d_cnt[d4.x], 1);
        atomicAdd(&d_cnt[d4.y], 1);
        atomicAdd(&d_cnt[d4.z], 1);
        atomicAdd(&d_cnt[d4.w], 1);
    } else {
        int i = (b - CNT_BLK) * 256 + t;           // half2 slot
        if (i < N_NODES * 24) {
            int n = i / 24, c = i - n * 24;
            int f0 = 2 * c, f1 = 2 * c + 1;
            float v0 = (f0 < F1) ? x[n * F1 + f0] : 0.f;
            float v1 = (f1 < F1) ? x[n * F1 + f1] : 0.f;
            ((__half2*)d_xh)[n * 24 + c] = __floats2half2_rn(v0, v1);
        }
    }
}

// ---------------- K1: fused exclusive scan (grid barrier), + gmax reset, + cnt reset ----------------
__global__ __launch_bounds__(1024) void scan_kernel() {
    __shared__ int ws[32];
    __shared__ int sc[4];
    const int b = blockIdx.x, t = threadIdx.x;
    const int lane = t & 31, wid = t >> 5;
    const int i = b * 1024 + t;

    if (i < N_GRAPHS * F2) d_gmax[i] = (int)0x807FFFFFu;   // fkey(-inf)

    const int v = (i < N_NODES) ? d_cnt[i] : 0;

    // ---- phase A: block sum -> d_bsum[b] ----
    int s = v;
#pragma unroll
    for (int o = 16; o > 0; o >>= 1) s += __shfl_down_sync(0xffffffffu, s, o);
    if (lane == 0) ws[wid] = s;
    __syncthreads();
    if (t < 32) {
        int xv = ws[t];
#pragma unroll
        for (int o = 16; o > 0; o >>= 1) xv += __shfl_down_sync(0xffffffffu, xv, o);
        if (t == 0) {
            d_bsum[b] = xv;
            __threadfence();
            atomicAdd(&g_ctr_a, 1);
        }
    }
    // ---- grid barrier: wait for all 98 block sums ----
    if (t == 0) { while (atomicAdd(&g_ctr_a, 0) < NB) { } }
    __syncthreads();
    __threadfence();

    // ---- phase B: inline prefix over block sums (carry for block b) ----
    if (t < 128) {
        int pv = (t < NB && t < b) ? d_bsum[t] : 0;
#pragma unroll
        for (int o = 16; o > 0; o >>= 1) pv += __shfl_down_sync(0xffffffffu, pv, o);
        if (lane == 0) sc[wid] = pv;
    }
    int incl = v;
#pragma unroll
    for (int o = 1; o < 32; o <<= 1) {
        int xv = __shfl_up_sync(0xffffffffu, incl, o);
        if (lane >= o) incl += xv;
    }
    if (lane == 31) ws[wid] = incl;
    __syncthreads();
    const int carry = sc[0] + sc[1] + sc[2] + sc[3];
    if (t < 32) {
        int xv = ws[t], xi = xv;
#pragma unroll
        for (int o = 1; o < 32; o <<= 1) {
            int y = __shfl_up_sync(0xffffffffu, xi, o);
            if (lane >= o) xi += y;
        }
        ws[t] = xi - xv;
    }
    __syncthreads();
    const int ex = carry + ws[wid] + (incl - v);
    if (i < N_NODES) {
        d_off[i] = ex;
        d_cur[i] = ex;
        d_cnt[i] = 0;                      // graph-replay invariant
        if (i == N_NODES - 1) d_off[N_NODES] = ex + v;
    }
    __syncthreads();
    if (t == 0) {
        int r = atomicAdd(&g_ctr_b, 1);
        if (r == NB - 1) { atomicExch(&g_ctr_a, 0); atomicExch(&g_ctr_b, 0); }
    }
}

// ---------------- K2: CSR fill, 4 edges/thread ----------------
__global__ void fill_kernel(const int* __restrict__ src, const int* __restrict__ dst) {
    int i = blockIdx.x * blockDim.x + threadIdx.x;
    if (i >= N_EDGES / 4) return;
    int4 s4 = __ldg(&((const int4*)src)[i]);
    int4 d4 = __ldg(&((const int4*)dst)[i]);
    int p0 = atomicAdd(&d_cur[d4.x], 1);
    int p1 = atomicAdd(&d_cur[d4.y], 1);
    int p2 = atomicAdd(&d_cur[d4.z], 1);
    int p3 = atomicAdd(&d_cur[d4.w], 1);
    d_csr_src[p0] = s4.x;
    d_csr_src[p1] = s4.y;
    d_csr_src[p2] = s4.z;
    d_csr_src[p3] = s4.w;
}

// ---------------- K3: mean aggregation: warp/node, 6 edges/iter, HADD2 accumulators ----------------
// 5 lanes cover halves 0..39 (35 real features + 5 zero-pads); 6 edge groups per warp.
// Inner body is 4 HADD2 per lane (no per-edge float conversion); fp32 only at epilogue.
__global__ __launch_bounds__(256) void agg_kernel() {
    int w = (blockIdx.x * blockDim.x + threadIdx.x) >> 5;
    int lane = threadIdx.x & 31;
    if (w >= N_NODES) return;
    int g = lane / 5;            // edge group 0..5 (lanes 30,31 -> g=6, inactive)
    int p = lane - g * 5;        // 16B slice -> halves 8p..8p+7
    bool active = g < 6;
    int beg = d_off[w], end = d_off[w + 1];
    int deg = end - beg;

    unsigned a0 = 0u, a1 = 0u, a2 = 0u, a3 = 0u;   // 4x half2 accumulators (0x0 == +0,+0)

    const uint4* __restrict__ xh4 = (const uint4*)d_xh;
#pragma unroll 4
    for (int e0 = beg; e0 < end; e0 += 6) {
        int e = e0 + g;
        uint4 v = make_uint4(0u, 0u, 0u, 0u);
        if (active && e < end) {
            int s = d_csr_src[e];
            v = __ldg(&xh4[(long)s * 6 + p]);
        }
        a0 = hadd2u(a0, v.x);
        a1 = hadd2u(a1, v.y);
        a2 = hadd2u(a2, v.z);
        a3 = hadd2u(a3, v.w);
    }

    // tree-reduce 6 groups in half2: (g, g+3) pairs, then 3-way gather
    a0 = hadd2u(a0, __shfl_sync(0xffffffffu, a0, lane + 15));
    a1 = hadd2u(a1, __shfl_sync(0xffffffffu, a1, lane + 15));
    a2 = hadd2u(a2, __shfl_sync(0xffffffffu, a2, lane + 15));
    a3 = hadd2u(a3, __shfl_sync(0xffffffffu, a3, lane + 15));
    unsigned b0 = __shfl_sync(0xffffffffu, a0, lane + 5);
    unsigned b1 = __shfl_sync(0xffffffffu, a1, lane + 5);
    unsigned b2 = __shfl_sync(0xffffffffu, a2, lane + 5);
    unsigned b3 = __shfl_sync(0xffffffffu, a3, lane + 5);
    unsigned c0 = __shfl_sync(0xffffffffu, a0, lane + 10);
    unsigned c1 = __shfl_sync(0xffffffffu, a1, lane + 10);
    unsigned c2 = __shfl_sync(0xffffffffu, a2, lane + 10);
    unsigned c3 = __shfl_sync(0xffffffffu, a3, lane + 10);
    a0 = hadd2u(hadd2u(a0, b0), c0);
    a1 = hadd2u(hadd2u(a1, b1), c1);
    a2 = hadd2u(hadd2u(a2, b2), c2);
    a3 = hadd2u(hadd2u(a3, b3), c3);

    if (lane < 5) {
        float inv = 1.0f / fmaxf((float)deg, 1.0f);
        float2 f0 = __half22float2(*(__half2*)&a0);
        float2 f1 = __half22float2(*(__half2*)&a1);
        float2 f2 = __half22float2(*(__half2*)&a2);
        float2 f3 = __half22float2(*(__half2*)&a3);
        __half2 h0 = __floats2half2_rn(f0.x * inv, f0.y * inv);
        __half2 h1 = __floats2half2_rn(f1.x * inv, f1.y * inv);
        __half2 h2 = __floats2half2_rn(f2.x * inv, f2.y * inv);
        __half2 h3 = __floats2half2_rn(f3.x * inv, f3.y * inv);
        uint4 u;
        u.x = *(unsigned*)&h0; u.y = *(unsigned*)&h1;
        u.z = *(unsigned*)&h2; u.w = *(unsigned*)&h3;
        ((uint4*)(d_a2 + (long)w * APAD))[lane] = u;   // halves 0..39; 40..47 stay 0
    }
}

// ---------------- K4: lin1 fp32 FFMA2, out = relu([agg|x] @ W1 + b1) -> fp16 h1 rows ----------------
__global__ __launch_bounds__(256) void lin1_kernel(
    const float* __restrict__ xin, const float* __restrict__ Wl,
    const float* __restrict__ bl, const float* __restrict__ Wr)
{
    __shared__ __align__(16) float sAT[KDIM][36];
    __shared__ float sW[KDIM * F1];
    __shared__ float sbl[F1];

    const int tid = threadIdx.x;
    const int jt = tid & 31;
    const int mt = tid >> 5;
    const int base_n = blockIdx.x * 32;

    for (int idx = tid; idx < KDIM * F1; idx += 256) {
        int k = idx / F1, j = idx - k * F1;
        sW[idx] = (k < F1) ? Wl[k * F1 + j] : Wr[(k - F1) * F1 + j];
    }
    if (tid < F1) sbl[tid] = bl[tid];
    for (int idx = tid; idx < 32 * F1; idx += 256) {
        int m = idx & 31, k = idx >> 5;
        long n = base_n + m;
        sAT[k][m]      = __half2float(d_a2[n * APAD + k]);
        sAT[k + F1][m] = xin[n * F1 + k];
    }
    __syncthreads();

    unsigned long long acc2[2][2];
#pragma unroll
    for (int p = 0; p < 2; p++)
#pragma unroll
        for (int c = 0; c < 2; c++) acc2[p][c] = 0ULL;

#pragma unroll 2
    for (int k = 0; k < KDIM; k++) {
        float4 a4 = *(const float4*)&sAT[k][mt * 4];
        unsigned long long a01, a23;
        PACK_F32X2(a01, a4.x, a4.y);
        PACK_F32X2(a23, a4.z, a4.w);
#pragma unroll
        for (int c = 0; c < 2; c++) {
            int j = jt + 32 * c;
            float w = (j < F1) ? sW[k * F1 + j] : 0.f;
            unsigned long long ww;
            PACK_F32X2(ww, w, w);
            FMA_F32X2(acc2[0][c], a01, ww, acc2[0][c]);
            FMA_F32X2(acc2[1][c], a23, ww, acc2[1][c]);
        }
    }

    const int n0 = base_n + mt * 4;
    float v[4];
#pragma unroll
    for (int c = 0; c < 2; c++) {
        int j = jt + 32 * c;
        if (j < F1) {
            UNPACK_F32X2(v[0], v[1], acc2[0][c]);
            UNPACK_F32X2(v[2], v[3], acc2[1][c]);
#pragma unroll
            for (int r = 0; r < 4; r++) {
                float o = fmaxf(v[r] + sbl[j], 0.f);
                d_xh[(long)(n0 + r) * RPAD + j] = __float2half(o);
            }
        }
    }
}

// ---------------- K6: lin2 + max-pool: HMMA m16n8k16, 64 nodes/block ----------------
__global__ __launch_bounds__(256) void mma_pool_kernel(
    const float* __restrict__ Wl, const float* __restrict__ bl,
    const float* __restrict__ Wr, const int* __restrict__ batch)
{
    __shared__ __align__(16) __half sA[64 * 88];
    __shared__ __align__(16) __half sB[128 * 88];
    __shared__ float sbl[F2];
    __shared__ int   sgm[F2];

    const int tid = threadIdx.x;
    const int w = tid >> 5;
    const int lane = tid & 31;
    const int gid = lane >> 2;
    const int tig = lane & 3;
    const int base = blockIdx.x * 64;

    for (int idx = tid; idx < 64 * 80; idx += 256) {
        int m = idx / 80, k = idx - (idx / 80) * 80;
        long n = base + m;
        __half v = __ushort_as_half((unsigned short)0);
        if (n < N_NODES) {
            if (k < F1) v = d_a2[n * APAD + k];
            else if (k < KDIM) v = d_xh[n * RPAD + (k - F1)];
        }
        sA[m * 88 + k] = v;
    }
    for (int idx = tid; idx < 80 * F2; idx += 256) {
        int k = idx >> 7, n = idx & 127;
        float v = 0.f;
        if (k < F1) v = Wl[k * F2 + n];
        else if (k < KDIM) v = Wr[(k - F1) * F2 + n];
        sB[n * 88 + k] = __float2half(v);
    }
    if (tid < F2) { sbl[tid] = bl[tid]; sgm[tid] = (int)0x80000000; }
    __syncthreads();

    const int wm = w & 3;
    const int wn = (w >> 2) * 8;
    float acc[8][4];
#pragma unroll
    for (int nt = 0; nt < 8; nt++)
#pragma unroll
        for (int c = 0; c < 4; c++) acc[nt][c] = 0.f;

#pragma unroll
    for (int kc = 0; kc < 5; kc++) {
        const int k0 = kc * 16;
        unsigned a[4];
        const int ra = (wm * 16 + gid) * 88 + k0 + tig * 2;
        a[0] = *(const unsigned*)&sA[ra];
        a[1] = *(const unsigned*)&sA[ra + 8 * 88];
        a[2] = *(const unsigned*)&sA[ra + 8];
        a[3] = *(const unsigned*)&sA[ra + 8 * 88 + 8];
#pragma unroll
        for (int nt = 0; nt < 8; nt++) {
            unsigned b[2];
            const int rb = ((wn + nt) * 8 + gid) * 88 + k0 + tig * 2;
            b[0] = *(const unsigned*)&sB[rb];
            b[1] = *(const unsigned*)&sB[rb + 8];
            mma16816(acc[nt], a, b);
        }
    }

    const int r0 = base + wm * 16 + gid;
    const int r1 = r0 + 8;
    const bool full = (base + 63 < N_NODES);
    const int gfirst = batch[base];
    const bool single = full && (gfirst == batch[base + 63]);

    if (single) {
#pragma unroll
        for (int nt = 0; nt < 8; nt++) {
            int c0 = (wn + nt) * 8 + tig * 2;
            int k0v = max(fkey(acc[nt][0] + sbl[c0]),     fkey(acc[nt][2] + sbl[c0]));
            int k1v = max(fkey(acc[nt][1] + sbl[c0 + 1]), fkey(acc[nt][3] + sbl[c0 + 1]));
            atomicMax(&sgm[c0], k0v);
            atomicMax(&sgm[c0 + 1], k1v);
        }
        __syncthreads();
        if (tid < F2) atomicMax(&d_gmax[gfirst * F2 + tid], sgm[tid]);
    } else {
        int b0 = (r0 < N_NODES) ? batch[r0] : -1;
        int b1 = (r1 < N_NODES) ? batch[r1] : -1;
#pragma unroll
        for (int nt = 0; nt < 8; nt++) {
            int c0 = (wn + nt) * 8 + tig * 2;
            if (b0 >= 0) {
                atomicMax(&d_gmax[b0 * F2 + c0],     fkey(acc[nt][0] + sbl[c0]));
                atomicMax(&d_gmax[b0 * F2 + c0 + 1], fkey(acc[nt][1] + sbl[c0 + 1]));
            }
            if (b1 >= 0) {
                atomicMax(&d_gmax[b1 * F2 + c0],     fkey(acc[nt][2] + sbl[c0]));
                atomicMax(&d_gmax[b1 * F2 + c0 + 1], fkey(acc[nt][3] + sbl[c0 + 1]));
            }
        }
    }
}

// ---------------- K7: FC head ----------------
__global__ __launch_bounds__(128) void head_kernel(
    const float* __restrict__ Wg1, const float* __restrict__ bg1,
    const float* __restrict__ Wg2, const float* __restrict__ bg2,
    const float* __restrict__ Wo,  const float* __restrict__ bo,
    float* __restrict__ out)
{
    int g = blockIdx.x, j = threadIdx.x;
    __shared__ float r0[F2], r1[F2];
    __shared__ float wred[4];
    int key = d_gmax[g * F2 + j];
    key = key >= 0 ? key : (key ^ 0x7FFFFFFF);
    r0[j] = __int_as_float(key);
    __syncthreads();
    float acc = bg1[j];
#pragma unroll 8
    for (int k = 0; k < F2; k++) acc += r0[k] * Wg1[k * F2 + j];
    r1[j] = fmaxf(acc, 0.f);
    __syncthreads();
    acc = bg2[j];
#pragma unroll 8
    for (int k = 0; k < F2; k++) acc += r1[k] * Wg2[k * F2 + j];
    float v = fmaxf(acc, 0.f) * Wo[j];
#pragma unroll
    for (int s = 16; s > 0; s >>= 1) v += __shfl_down_sync(0xffffffffu, v, s);
    if ((j & 31) == 0) wred[j >> 5] = v;
    __syncthreads();
    if (j == 0) out[g] = wred[0] + wred[1] + wred[2] + wred[3] + bo[0];
}

// ---------------- launcher (8 kernels; agg1 at capture index 3) ----------------
extern "C" void kernel_launch(void* const* d_in, const int* in_sizes, int n_in,
                              void* d_out, int out_size) {
    const float* x    = (const float*)d_in[0];
    const int*   ei   = (const int*)d_in[1];
    const int*   bat  = (const int*)d_in[2];
    const float* Wl1  = (const float*)d_in[3];
    const float* bl1  = (const float*)d_in[4];
    const float* Wr1  = (const float*)d_in[5];
    const float* Wl2  = (const float*)d_in[6];
    const float* bl2  = (const float*)d_in[7];
    const float* Wr2  = (const float*)d_in[8];
    const float* Wg1  = (const float*)d_in[9];
    const float* bg1  = (const float*)d_in[10];
    const float* Wg2  = (const float*)d_in[11];
    const float* bg2  = (const float*)d_in[12];
    const float* Wo   = (const float*)d_in[13];
    const float* bo   = (const float*)d_in[14];
    float* out = (float*)d_out;

    const int* src = ei;
    const int* dst = ei + N_EDGES;

    pre_kernel<<<CNT_BLK + CONV_BLK, 256>>>(x, dst);                    // 0
    scan_kernel<<<NB, 1024>>>();                                        // 1
    fill_kernel<<<(N_EDGES / 4 + 255) / 256, 256>>>(src, dst);          // 2

    agg_kernel<<<(N_NODES * 32 + 255) / 256, 256>>>();                  // 3 <- profiled
    lin1_kernel<<<N_NODES / 32, 256>>>(x, Wl1, bl1, Wr1);               // 4

    agg_kernel<<<(N_NODES * 32 + 255) / 256, 256>>>();                  // 5
    mma_pool_kernel<<<(N_NODES + 63) / 64, 256>>>(Wl2, bl2, Wr2, bat);  // 6

    head_kernel<<<N_GRAPHS, F2>>>(Wg1, bg1, Wg2, bg2, Wo, bo, out);     // 7
}

// round 12
// speedup vs baseline: 1.1590x; 1.0264x over previous
#include <cuda_runtime.h>
#include <cuda_fp16.h>

#define N_NODES  100000
#define N_EDGES  3200000
#define N_GRAPHS 512
#define F1 35
#define F2 128
#define KDIM 70
#define RPAD 64                         // fp16 row padded to 64 halves = 128B = 1 full line
#define APAD 48                         // agg fp16 row stride (halves); read linearly only
#define NB ((N_NODES + 1023) / 1024)    // 98 scan blocks
#define CNT_BLK (N_EDGES / 4 / 256)     // 3125 (4 edges/thread)
#define CONV_BLK (N_NODES * 32 / 256)   // 12500 (N_NODES*32 half2 slots)

// ---------------- device scratch (zero-initialized at load) ----------------
__device__ int    d_cnt[N_NODES];        // re-zeroed by scan each call
__device__ int    d_off[N_NODES + 1];
__device__ int    d_cur[N_NODES];
__device__ int    d_bsum[NB];
__device__ int    g_ctr_a, g_ctr_b;      // grid barrier counters (reset each call)
__device__ int    d_csr_src[N_EDGES];
__device__ __half d_a2[N_NODES * APAD];  // fp16 agg rows; halves 40..47 stay 0 forever
__device__ __half d_xh[N_NODES * RPAD];  // 128B-aligned fp16 feature rows; pads stay 0
__device__ int    d_gmax[N_GRAPHS * F2];

#define FMA_F32X2(d, a, b, c) \
    asm("fma.rn.f32x2 %0, %1, %2, %3;" : "=l"(d) : "l"(a), "l"(b), "l"(c))
#define PACK_F32X2(out, lo, hi) \
    asm("mov.b64 %0, {%1, %2};" : "=l"(out) : "f"(lo), "f"(hi))
#define UNPACK_F32X2(lo, hi, in) \
    asm("mov.b64 {%0, %1}, %2;" : "=f"(lo), "=f"(hi) : "l"(in))

__device__ __forceinline__ int fkey(float f) {
    int i = __float_as_int(f);
    return i >= 0 ? i : (i ^ 0x7FFFFFFF);
}

__device__ __forceinline__ unsigned hadd2u(unsigned a, unsigned b) {
    unsigned r;
    asm("add.rn.f16x2 %0, %1, %2;" : "=r"(r) : "r"(a), "r"(b));
    return r;
}

// m16n8k16 fp16 MMA, fp32 accumulate (row-major A, col-major B)
__device__ __forceinline__ void mma16816(float* d, const unsigned* a, const unsigned* b) {
    asm volatile(
        "mma.sync.aligned.m16n8k16.row.col.f32.f16.f16.f32 "
        "{%0,%1,%2,%3}, {%4,%5,%6,%7}, {%8,%9}, {%0,%1,%2,%3};\n"
        : "+f"(d[0]), "+f"(d[1]), "+f"(d[2]), "+f"(d[3])
        : "r"(a[0]), "r"(a[1]), "r"(a[2]), "r"(a[3]), "r"(b[0]), "r"(b[1]));
}

// ---------------- K0: degree count (4 edges/thread) + conv(x -> fp16 rows), fused ----------------
__global__ void pre_kernel(const float* __restrict__ x, const int* __restrict__ dst) {
    int b = blockIdx.x, t = threadIdx.x;
    if (b < CNT_BLK) {
        int i = b * 256 + t;
        int4 d4 = __ldg(&((const int4*)dst)[i]);
        atomicAdd(&d_cnt[d4.x], 1);
        atomicAdd(&d_cnt[d4.y], 1);
        atomicAdd(&d_cnt[d4.z], 1);
        atomicAdd(&d_cnt[d4.w], 1);
    } else {
        int i = (b - CNT_BLK) * 256 + t;           // half2 slot
        if (i < N_NODES * 32) {
            int n = i >> 5, c = i & 31;
            int f0 = 2 * c, f1 = 2 * c + 1;
            float v0 = (f0 < F1) ? x[n * F1 + f0] : 0.f;
            float v1 = (f1 < F1) ? x[n * F1 + f1] : 0.f;
            ((__half2*)d_xh)[i] = __floats2half2_rn(v0, v1);
        }
    }
}

// ---------------- K1: fused exclusive scan (grid barrier), + gmax reset, + cnt reset ----------------
__global__ __launch_bounds__(1024) void scan_kernel() {
    __shared__ int ws[32];
    __shared__ int sc[4];
    const int b = blockIdx.x, t = threadIdx.x;
    const int lane = t & 31, wid = t >> 5;
    const int i = b * 1024 + t;

    if (i < N_GRAPHS * F2) d_gmax[i] = (int)0x807FFFFFu;   // fkey(-inf)

    const int v = (i < N_NODES) ? d_cnt[i] : 0;

    // ---- phase A: block sum -> d_bsum[b] ----
    int s = v;
#pragma unroll
    for (int o = 16; o > 0; o >>= 1) s += __shfl_down_sync(0xffffffffu, s, o);
    if (lane == 0) ws[wid] = s;
    __syncthreads();
    if (t < 32) {
        int xv = ws[t];
#pragma unroll
        for (int o = 16; o > 0; o >>= 1) xv += __shfl_down_sync(0xffffffffu, xv, o);
        if (t == 0) {
            d_bsum[b] = xv;
            __threadfence();
            atomicAdd(&g_ctr_a, 1);
        }
    }
    // ---- grid barrier ----
    if (t == 0) { while (atomicAdd(&g_ctr_a, 0) < NB) { } }
    __syncthreads();
    __threadfence();

    // ---- phase B: inline prefix over block sums ----
    if (t < 128) {
        int pv = (t < NB && t < b) ? d_bsum[t] : 0;
#pragma unroll
        for (int o = 16; o > 0; o >>= 1) pv += __shfl_down_sync(0xffffffffu, pv, o);
        if (lane == 0) sc[wid] = pv;
    }
    int incl = v;
#pragma unroll
    for (int o = 1; o < 32; o <<= 1) {
        int xv = __shfl_up_sync(0xffffffffu, incl, o);
        if (lane >= o) incl += xv;
    }
    if (lane == 31) ws[wid] = incl;
    __syncthreads();
    const int carry = sc[0] + sc[1] + sc[2] + sc[3];
    if (t < 32) {
        int xv = ws[t], xi = xv;
#pragma unroll
        for (int o = 1; o < 32; o <<= 1) {
            int y = __shfl_up_sync(0xffffffffu, xi, o);
            if (lane >= o) xi += y;
        }
        ws[t] = xi - xv;
    }
    __syncthreads();
    const int ex = carry + ws[wid] + (incl - v);
    if (i < N_NODES) {
        d_off[i] = ex;
        d_cur[i] = ex;
        d_cnt[i] = 0;                      // graph-replay invariant
        if (i == N_NODES - 1) d_off[N_NODES] = ex + v;
    }
    __syncthreads();
    if (t == 0) {
        int r = atomicAdd(&g_ctr_b, 1);
        if (r == NB - 1) { atomicExch(&g_ctr_a, 0); atomicExch(&g_ctr_b, 0); }
    }
}

// ---------------- K2: CSR fill, 4 edges/thread ----------------
__global__ void fill_kernel(const int* __restrict__ src, const int* __restrict__ dst) {
    int i = blockIdx.x * blockDim.x + threadIdx.x;
    if (i >= N_EDGES / 4) return;
    int4 s4 = __ldg(&((const int4*)src)[i]);
    int4 d4 = __ldg(&((const int4*)dst)[i]);
    int p0 = atomicAdd(&d_cur[d4.x], 1);
    int p1 = atomicAdd(&d_cur[d4.y], 1);
    int p2 = atomicAdd(&d_cur[d4.z], 1);
    int p3 = atomicAdd(&d_cur[d4.w], 1);
    d_csr_src[p0] = s4.x;
    d_csr_src[p1] = s4.y;
    d_csr_src[p2] = s4.z;
    d_csr_src[p3] = s4.w;
}

// ---------------- K3: mean aggregation: warp/node, 4 edges/iter, 1 line/edge, HADD2 ----------------
// 8 lanes x 16B cover one 128B row exactly; 4 edge groups/warp; all 32 lanes active.
__global__ __launch_bounds__(256) void agg_kernel() {
    int w = (blockIdx.x * blockDim.x + threadIdx.x) >> 5;
    int lane = threadIdx.x & 31;
    if (w >= N_NODES) return;
    int g = lane >> 3;           // edge group 0..3
    int p = lane & 7;            // 16B slice -> halves 8p..8p+7
    int beg = d_off[w], end = d_off[w + 1];
    int deg = end - beg;

    unsigned a0 = 0u, a1 = 0u, a2 = 0u, a3 = 0u;   // 4x half2 accumulators

    const uint4* __restrict__ xh4 = (const uint4*)d_xh;   // row = 8 uint4
#pragma unroll 4
    for (int e0 = beg; e0 < end; e0 += 4) {
        int e = e0 + g;
        uint4 v = make_uint4(0u, 0u, 0u, 0u);
        if (e < end) {
            int s = d_csr_src[e];
            v = __ldg(&xh4[(long)s * 8 + p]);
        }
        a0 = hadd2u(a0, v.x);
        a1 = hadd2u(a1, v.y);
        a2 = hadd2u(a2, v.z);
        a3 = hadd2u(a3, v.w);
    }

    // butterfly-reduce the 4 edge groups (xor 8, xor 16)
    a0 = hadd2u(a0, __shfl_xor_sync(0xffffffffu, a0, 8));
    a1 = hadd2u(a1, __shfl_xor_sync(0xffffffffu, a1, 8));
    a2 = hadd2u(a2, __shfl_xor_sync(0xffffffffu, a2, 8));
    a3 = hadd2u(a3, __shfl_xor_sync(0xffffffffu, a3, 8));
    a0 = hadd2u(a0, __shfl_xor_sync(0xffffffffu, a0, 16));
    a1 = hadd2u(a1, __shfl_xor_sync(0xffffffffu, a1, 16));
    a2 = hadd2u(a2, __shfl_xor_sync(0xffffffffu, a2, 16));
    a3 = hadd2u(a3, __shfl_xor_sync(0xffffffffu, a3, 16));

    if (lane < 5) {
        float inv = 1.0f / fmaxf((float)deg, 1.0f);
        float2 f0 = __half22float2(*(__half2*)&a0);
        float2 f1 = __half22float2(*(__half2*)&a1);
        float2 f2 = __half22float2(*(__half2*)&a2);
        float2 f3 = __half22float2(*(__half2*)&a3);
        __half2 h0 = __floats2half2_rn(f0.x * inv, f0.y * inv);
        __half2 h1 = __floats2half2_rn(f1.x * inv, f1.y * inv);
        __half2 h2 = __floats2half2_rn(f2.x * inv, f2.y * inv);
        __half2 h3 = __floats2half2_rn(f3.x * inv, f3.y * inv);
        uint4 u;
        u.x = *(unsigned*)&h0; u.y = *(unsigned*)&h1;
        u.z = *(unsigned*)&h2; u.w = *(unsigned*)&h3;
        ((uint4*)(d_a2 + (long)w * APAD))[lane] = u;   // halves 0..39 (35..39 are zeros)
    }
}

// ---------------- K4: lin1 fp32 FFMA2, out = relu([agg|x] @ W1 + b1) -> fp16 h1 rows ----------------
__global__ __launch_bounds__(256) void lin1_kernel(
    const float* __restrict__ xin, const float* __restrict__ Wl,
    const float* __restrict__ bl, const float* __restrict__ Wr)
{
    __shared__ __align__(16) float sAT[KDIM][36];
    __shared__ float sW[KDIM * F1];
    __shared__ float sbl[F1];

    const int tid = threadIdx.x;
    const int jt = tid & 31;
    const int mt = tid >> 5;
    const int base_n = blockIdx.x * 32;

    for (int idx = tid; idx < KDIM * F1; idx += 256) {
        int k = idx / F1, j = idx - k * F1;
        sW[idx] = (k < F1) ? Wl[k * F1 + j] : Wr[(k - F1) * F1 + j];
    }
    if (tid < F1) sbl[tid] = bl[tid];
    for (int idx = tid; idx < 32 * F1; idx += 256) {
        int m = idx & 31, k = idx >> 5;
        long n = base_n + m;
        sAT[k][m]      = __half2float(d_a2[n * APAD + k]);
        sAT[k + F1][m] = xin[n * F1 + k];
    }
    __syncthreads();

    unsigned long long acc2[2][2];
#pragma unroll
    for (int p = 0; p < 2; p++)
#pragma unroll
        for (int c = 0; c < 2; c++) acc2[p][c] = 0ULL;

#pragma unroll 2
    for (int k = 0; k < KDIM; k++) {
        float4 a4 = *(const float4*)&sAT[k][mt * 4];
        unsigned long long a01, a23;
        PACK_F32X2(a01, a4.x, a4.y);
        PACK_F32X2(a23, a4.z, a4.w);
#pragma unroll
        for (int c = 0; c < 2; c++) {
            int j = jt + 32 * c;
            float w = (j < F1) ? sW[k * F1 + j] : 0.f;
            unsigned long long ww;
            PACK_F32X2(ww, w, w);
            FMA_F32X2(acc2[0][c], a01, ww, acc2[0][c]);
            FMA_F32X2(acc2[1][c], a23, ww, acc2[1][c]);
        }
    }

    const int n0 = base_n + mt * 4;
    float v[4];
#pragma unroll
    for (int c = 0; c < 2; c++) {
        int j = jt + 32 * c;
        if (j < F1) {
            UNPACK_F32X2(v[0], v[1], acc2[0][c]);
            UNPACK_F32X2(v[2], v[3], acc2[1][c]);
#pragma unroll
            for (int r = 0; r < 4; r++) {
                float o = fmaxf(v[r] + sbl[j], 0.f);
                d_xh[(long)(n0 + r) * RPAD + j] = __float2half(o);
            }
        }
    }
}

// ---------------- K6: lin2 + max-pool: HMMA m16n8k16, 64 nodes/block ----------------
__global__ __launch_bounds__(256) void mma_pool_kernel(
    const float* __restrict__ Wl, const float* __restrict__ bl,
    const float* __restrict__ Wr, const int* __restrict__ batch)
{
    __shared__ __align__(16) __half sA[64 * 88];
    __shared__ __align__(16) __half sB[128 * 88];
    __shared__ float sbl[F2];
    __shared__ int   sgm[F2];

    const int tid = threadIdx.x;
    const int w = tid >> 5;
    const int lane = tid & 31;
    const int gid = lane >> 2;
    const int tig = lane & 3;
    const int base = blockIdx.x * 64;

    for (int idx = tid; idx < 64 * 80; idx += 256) {
        int m = idx / 80, k = idx - (idx / 80) * 80;
        long n = base + m;
        __half v = __ushort_as_half((unsigned short)0);
        if (n < N_NODES) {
            if (k < F1) v = d_a2[n * APAD + k];
            else if (k < KDIM) v = d_xh[n * RPAD + (k - F1)];
        }
        sA[m * 88 + k] = v;
    }
    for (int idx = tid; idx < 80 * F2; idx += 256) {
        int k = idx >> 7, n = idx & 127;
        float v = 0.f;
        if (k < F1) v = Wl[k * F2 + n];
        else if (k < KDIM) v = Wr[(k - F1) * F2 + n];
        sB[n * 88 + k] = __float2half(v);
    }
    if (tid < F2) { sbl[tid] = bl[tid]; sgm[tid] = (int)0x80000000; }
    __syncthreads();

    const int wm = w & 3;
    const int wn = (w >> 2) * 8;
    float acc[8][4];
#pragma unroll
    for (int nt = 0; nt < 8; nt++)
#pragma unroll
        for (int c = 0; c < 4; c++) acc[nt][c] = 0.f;

#pragma unroll
    for (int kc = 0; kc < 5; kc++) {
        const int k0 = kc * 16;
        unsigned a[4];
        const int ra = (wm * 16 + gid) * 88 + k0 + tig * 2;
        a[0] = *(const unsigned*)&sA[ra];
        a[1] = *(const unsigned*)&sA[ra + 8 * 88];
        a[2] = *(const unsigned*)&sA[ra + 8];
        a[3] = *(const unsigned*)&sA[ra + 8 * 88 + 8];
#pragma unroll
        for (int nt = 0; nt < 8; nt++) {
            unsigned b[2];
            const int rb = ((wn + nt) * 8 + gid) * 88 + k0 + tig * 2;
            b[0] = *(const unsigned*)&sB[rb];
            b[1] = *(const unsigned*)&sB[rb + 8];
            mma16816(acc[nt], a, b);
        }
    }

    const int r0 = base + wm * 16 + gid;
    const int r1 = r0 + 8;
    const bool full = (base + 63 < N_NODES);
    const int gfirst = batch[base];
    const bool single = full && (gfirst == batch[base + 63]);

    if (single) {
#pragma unroll
        for (int nt = 0; nt < 8; nt++) {
            int c0 = (wn + nt) * 8 + tig * 2;
            int k0v = max(fkey(acc[nt][0] + sbl[c0]),     fkey(acc[nt][2] + sbl[c0]));
            int k1v = max(fkey(acc[nt][1] + sbl[c0 + 1]), fkey(acc[nt][3] + sbl[c0 + 1]));
            atomicMax(&sgm[c0], k0v);
            atomicMax(&sgm[c0 + 1], k1v);
        }
        __syncthreads();
        if (tid < F2) atomicMax(&d_gmax[gfirst * F2 + tid], sgm[tid]);
    } else {
        int b0 = (r0 < N_NODES) ? batch[r0] : -1;
        int b1 = (r1 < N_NODES) ? batch[r1] : -1;
#pragma unroll
        for (int nt = 0; nt < 8; nt++) {
            int c0 = (wn + nt) * 8 + tig * 2;
            if (b0 >= 0) {
                atomicMax(&d_gmax[b0 * F2 + c0],     fkey(acc[nt][0] + sbl[c0]));
                atomicMax(&d_gmax[b0 * F2 + c0 + 1], fkey(acc[nt][1] + sbl[c0 + 1]));
            }
            if (b1 >= 0) {
                atomicMax(&d_gmax[b1 * F2 + c0],     fkey(acc[nt][2] + sbl[c0]));
                atomicMax(&d_gmax[b1 * F2 + c0 + 1], fkey(acc[nt][3] + sbl[c0 + 1]));
            }
        }
    }
}

// ---------------- K7: FC head ----------------
__global__ __launch_bounds__(128) void head_kernel(
    const float* __restrict__ Wg1, const float* __restrict__ bg1,
    const float* __restrict__ Wg2, const float* __restrict__ bg2,
    const float* __restrict__ Wo,  const float* __restrict__ bo,
    float* __restrict__ out)
{
    int g = blockIdx.x, j = threadIdx.x;
    __shared__ float r0[F2], r1[F2];
    __shared__ float wred[4];
    int key = d_gmax[g * F2 + j];
    key = key >= 0 ? key : (key ^ 0x7FFFFFFF);
    r0[j] = __int_as_float(key);
    __syncthreads();
    float acc = bg1[j];
#pragma unroll 8
    for (int k = 0; k < F2; k++) acc += r0[k] * Wg1[k * F2 + j];
    r1[j] = fmaxf(acc, 0.f);
    __syncthreads();
    acc = bg2[j];
#pragma unroll 8
    for (int k = 0; k < F2; k++) acc += r1[k] * Wg2[k * F2 + j];
    float v = fmaxf(acc, 0.f) * Wo[j];
#pragma unroll
    for (int s = 16; s > 0; s >>= 1) v += __shfl_down_sync(0xffffffffu, v, s);
    if ((j & 31) == 0) wred[j >> 5] = v;
    __syncthreads();
    if (j == 0) out[g] = wred[0] + wred[1] + wred[2] + wred[3] + bo[0];
}

// ---------------- launcher (8 kernels; agg1 at capture index 3) ----------------
extern "C" void kernel_launch(void* const* d_in, const int* in_sizes, int n_in,
                              void* d_out, int out_size) {
    const float* x    = (const float*)d_in[0];
    const int*   ei   = (const int*)d_in[1];
    const int*   bat  = (const int*)d_in[2];
    const float* Wl1  = (const float*)d_in[3];
    const float* bl1  = (const float*)d_in[4];
    const float* Wr1  = (const float*)d_in[5];
    const float* Wl2  = (const float*)d_in[6];
    const float* bl2  = (const float*)d_in[7];
    const float* Wr2  = (const float*)d_in[8];
    const float* Wg1  = (const float*)d_in[9];
    const float* bg1  = (const float*)d_in[10];
    const float* Wg2  = (const float*)d_in[11];
    const float* bg2  = (const float*)d_in[12];
    const float* Wo   = (const float*)d_in[13];
    const float* bo   = (const float*)d_in[14];
    float* out = (float*)d_out;

    const int* src = ei;
    const int* dst = ei + N_EDGES;

    pre_kernel<<<CNT_BLK + CONV_BLK, 256>>>(x, dst);                    // 0
    scan_kernel<<<NB, 1024>>>();                                        // 1
    fill_kernel<<<(N_EDGES / 4 + 255) / 256, 256>>>(src, dst);          // 2

    agg_kernel<<<(N_NODES * 32 + 255) / 256, 256>>>();                  // 3 <- profiled
    lin1_kernel<<<N_NODES / 32, 256>>>(x, Wl1, bl1, Wr1);               // 4

    agg_kernel<<<(N_NODES * 32 + 255) / 256, 256>>>();                  // 5
    mma_pool_kernel<<<(N_NODES + 63) / 64, 256>>>(Wl2, bl2, Wr2, bat);  // 6

    head_kernel<<<N_GRAPHS, F2>>>(Wg1, bg1, Wg2, bg2, Wo, bo, out);     // 7
}

// round 13
// speedup vs baseline: 1.1611x; 1.0019x over previous
#include <cuda_runtime.h>
#include <cuda_fp16.h>

#define N_NODES  100000
#define N_EDGES  3200000
#define N_GRAPHS 512
#define F1 35
#define F2 128
#define KDIM 70
#define RPAD 64                         // fp16 row padded to 64 halves = 128B = 1 full line
#define APAD 48                         // agg fp16 row stride (halves); read linearly only
#define NB ((N_NODES + 1023) / 1024)    // 98 scan blocks
#define CNT_BLK (N_EDGES / 4 / 256)     // 3125 (4 edges/thread)
#define CONV_BLK (N_NODES * 32 / 256)   // 12500 (N_NODES*32 half2 slots)

// ---------------- device scratch (zero-initialized at load) ----------------
__device__ int    d_cnt[N_NODES];        // re-zeroed by scan each call
__device__ int    d_off[N_NODES + 1];
__device__ int    d_cur[N_NODES];
__device__ int    d_bsum[NB];
__device__ int    g_ctr_a, g_ctr_b;      // grid barrier counters (reset each call)
__device__ int    d_csr_src[N_EDGES];    // PRESCALED: src * 8 (uint4-row units)
__device__ __half d_a2[N_NODES * APAD];  // fp16 agg rows; halves 40..47 stay 0 forever
__device__ __half d_xh[N_NODES * RPAD];  // 128B-aligned fp16 feature rows; pads stay 0
__device__ int    d_gmax[N_GRAPHS * F2];

#define FMA_F32X2(d, a, b, c) \
    asm("fma.rn.f32x2 %0, %1, %2, %3;" : "=l"(d) : "l"(a), "l"(b), "l"(c))
#define PACK_F32X2(out, lo, hi) \
    asm("mov.b64 %0, {%1, %2};" : "=l"(out) : "f"(lo), "f"(hi))
#define UNPACK_F32X2(lo, hi, in) \
    asm("mov.b64 {%0, %1}, %2;" : "=f"(lo), "=f"(hi) : "l"(in))

__device__ __forceinline__ int fkey(float f) {
    int i = __float_as_int(f);
    return i >= 0 ? i : (i ^ 0x7FFFFFFF);
}

__device__ __forceinline__ unsigned hadd2u(unsigned a, unsigned b) {
    unsigned r;
    asm("add.rn.f16x2 %0, %1, %2;" : "=r"(r) : "r"(a), "r"(b));
    return r;
}

// m16n8k16 fp16 MMA, fp32 accumulate (row-major A, col-major B)
__device__ __forceinline__ void mma16816(float* d, const unsigned* a, const unsigned* b) {
    asm volatile(
        "mma.sync.aligned.m16n8k16.row.col.f32.f16.f16.f32 "
        "{%0,%1,%2,%3}, {%4,%5,%6,%7}, {%8,%9}, {%0,%1,%2,%3};\n"
        : "+f"(d[0]), "+f"(d[1]), "+f"(d[2]), "+f"(d[3])
        : "r"(a[0]), "r"(a[1]), "r"(a[2]), "r"(a[3]), "r"(b[0]), "r"(b[1]));
}

// ---------------- K0: degree count (4 edges/thread) + conv(x -> fp16 rows), fused ----------------
__global__ void pre_kernel(const float* __restrict__ x, const int* __restrict__ dst) {
    int b = blockIdx.x, t = threadIdx.x;
    if (b < CNT_BLK) {
        int i = b * 256 + t;
        int4 d4 = __ldg(&((const int4*)dst)[i]);
        atomicAdd(&d_cnt[d4.x], 1);
        atomicAdd(&d_cnt[d4.y], 1);
        atomicAdd(&d_cnt[d4.z], 1);
        atomicAdd(&d_cnt[d4.w], 1);
    } else {
        int i = (b - CNT_BLK) * 256 + t;           // half2 slot
        if (i < N_NODES * 32) {
            int n = i >> 5, c = i & 31;
            int f0 = 2 * c, f1 = 2 * c + 1;
            float v0 = (f0 < F1) ? x[n * F1 + f0] : 0.f;
            float v1 = (f1 < F1) ? x[n * F1 + f1] : 0.f;
            ((__half2*)d_xh)[i] = __floats2half2_rn(v0, v1);
        }
    }
}

// ---------------- K1: fused exclusive scan (grid barrier), + gmax reset, + cnt reset ----------------
__global__ __launch_bounds__(1024) void scan_kernel() {
    __shared__ int ws[32];
    __shared__ int sc[4];
    const int b = blockIdx.x, t = threadIdx.x;
    const int lane = t & 31, wid = t >> 5;
    const int i = b * 1024 + t;

    if (i < N_GRAPHS * F2) d_gmax[i] = (int)0x807FFFFFu;   // fkey(-inf)

    const int v = (i < N_NODES) ? d_cnt[i] : 0;

    // ---- phase A: block sum -> d_bsum[b] ----
    int s = v;
#pragma unroll
    for (int o = 16; o > 0; o >>= 1) s += __shfl_down_sync(0xffffffffu, s, o);
    if (lane == 0) ws[wid] = s;
    __syncthreads();
    if (t < 32) {
        int xv = ws[t];
#pragma unroll
        for (int o = 16; o > 0; o >>= 1) xv += __shfl_down_sync(0xffffffffu, xv, o);
        if (t == 0) {
            d_bsum[b] = xv;
            __threadfence();
            atomicAdd(&g_ctr_a, 1);
        }
    }
    // ---- grid barrier ----
    if (t == 0) { while (atomicAdd(&g_ctr_a, 0) < NB) { } }
    __syncthreads();
    __threadfence();

    // ---- phase B: inline prefix over block sums ----
    if (t < 128) {
        int pv = (t < NB && t < b) ? d_bsum[t] : 0;
#pragma unroll
        for (int o = 16; o > 0; o >>= 1) pv += __shfl_down_sync(0xffffffffu, pv, o);
        if (lane == 0) sc[wid] = pv;
    }
    int incl = v;
#pragma unroll
    for (int o = 1; o < 32; o <<= 1) {
        int xv = __shfl_up_sync(0xffffffffu, incl, o);
        if (lane >= o) incl += xv;
    }
    if (lane == 31) ws[wid] = incl;
    __syncthreads();
    const int carry = sc[0] + sc[1] + sc[2] + sc[3];
    if (t < 32) {
        int xv = ws[t], xi = xv;
#pragma unroll
        for (int o = 1; o < 32; o <<= 1) {
            int y = __shfl_up_sync(0xffffffffu, xi, o);
            if (lane >= o) xi += y;
        }
        ws[t] = xi - xv;
    }
    __syncthreads();
    const int ex = carry + ws[wid] + (incl - v);
    if (i < N_NODES) {
        d_off[i] = ex;
        d_cur[i] = ex;
        d_cnt[i] = 0;                      // graph-replay invariant
        if (i == N_NODES - 1) d_off[N_NODES] = ex + v;
    }
    __syncthreads();
    if (t == 0) {
        int r = atomicAdd(&g_ctr_b, 1);
        if (r == NB - 1) { atomicExch(&g_ctr_a, 0); atomicExch(&g_ctr_b, 0); }
    }
}

// ---------------- K2: CSR fill, 4 edges/thread; stores PRESCALED src (*8) ----------------
__global__ void fill_kernel(const int* __restrict__ src, const int* __restrict__ dst) {
    int i = blockIdx.x * blockDim.x + threadIdx.x;
    if (i >= N_EDGES / 4) return;
    int4 s4 = __ldg(&((const int4*)src)[i]);
    int4 d4 = __ldg(&((const int4*)dst)[i]);
    int p0 = atomicAdd(&d_cur[d4.x], 1);
    int p1 = atomicAdd(&d_cur[d4.y], 1);
    int p2 = atomicAdd(&d_cur[d4.z], 1);
    int p3 = atomicAdd(&d_cur[d4.w], 1);
    d_csr_src[p0] = s4.x * 8;
    d_csr_src[p1] = s4.y * 8;
    d_csr_src[p2] = s4.z * 8;
    d_csr_src[p3] = s4.w * 8;
}

// ---------------- K3: mean aggregation: unpredicated quad loop + tail, HADD2 ----------------
// 8 lanes x 16B cover one 128B row exactly; 4 edge groups/warp.
__global__ __launch_bounds__(256) void agg_kernel() {
    int w = (blockIdx.x * blockDim.x + threadIdx.x) >> 5;
    int lane = threadIdx.x & 31;
    if (w >= N_NODES) return;
    int g = lane >> 3;           // edge group 0..3
    int p = lane & 7;            // 16B slice -> halves 8p..8p+7
    int beg = d_off[w], end = d_off[w + 1];
    int deg = end - beg;

    unsigned a0 = 0u, a1 = 0u, a2 = 0u, a3 = 0u;   // 4x half2 accumulators

    const uint4* __restrict__ xh4 = (const uint4*)d_xh;   // row = 8 uint4
    const int* __restrict__ csr = d_csr_src;              // prescaled (*8)

    int e = beg + g;
    int nq = deg >> 2;
#pragma unroll 4
    for (int q = 0; q < nq; q++, e += 4) {                // unpredicated main loop
        int s = __ldg(&csr[e]);
        uint4 v = __ldg(&xh4[s + p]);
        a0 = hadd2u(a0, v.x);
        a1 = hadd2u(a1, v.y);
        a2 = hadd2u(a2, v.z);
        a3 = hadd2u(a3, v.w);
    }
    int rem = deg & 3;
    if (g < rem) {                                        // predicated tail (<=3 edges)
        int s = __ldg(&csr[e]);
        uint4 v = __ldg(&xh4[s + p]);
        a0 = hadd2u(a0, v.x);
        a1 = hadd2u(a1, v.y);
        a2 = hadd2u(a2, v.z);
        a3 = hadd2u(a3, v.w);
    }

    // butterfly-reduce the 4 edge groups (xor 8, xor 16)
    a0 = hadd2u(a0, __shfl_xor_sync(0xffffffffu, a0, 8));
    a1 = hadd2u(a1, __shfl_xor_sync(0xffffffffu, a1, 8));
    a2 = hadd2u(a2, __shfl_xor_sync(0xffffffffu, a2, 8));
    a3 = hadd2u(a3, __shfl_xor_sync(0xffffffffu, a3, 8));
    a0 = hadd2u(a0, __shfl_xor_sync(0xffffffffu, a0, 16));
    a1 = hadd2u(a1, __shfl_xor_sync(0xffffffffu, a1, 16));
    a2 = hadd2u(a2, __shfl_xor_sync(0xffffffffu, a2, 16));
    a3 = hadd2u(a3, __shfl_xor_sync(0xffffffffu, a3, 16));

    if (lane < 5) {
        float inv = 1.0f / fmaxf((float)deg, 1.0f);
        float2 f0 = __half22float2(*(__half2*)&a0);
        float2 f1 = __half22float2(*(__half2*)&a1);
        float2 f2 = __half22float2(*(__half2*)&a2);
        float2 f3 = __half22float2(*(__half2*)&a3);
        __half2 h0 = __floats2half2_rn(f0.x * inv, f0.y * inv);
        __half2 h1 = __floats2half2_rn(f1.x * inv, f1.y * inv);
        __half2 h2 = __floats2half2_rn(f2.x * inv, f2.y * inv);
        __half2 h3 = __floats2half2_rn(f3.x * inv, f3.y * inv);
        uint4 u;
        u.x = *(unsigned*)&h0; u.y = *(unsigned*)&h1;
        u.z = *(unsigned*)&h2; u.w = *(unsigned*)&h3;
        ((uint4*)(d_a2 + (long)w * APAD))[lane] = u;   // halves 0..39 (35..39 are zeros)
    }
}

// ---------------- K4: lin1 fp32 FFMA2, out = relu([agg|x] @ W1 + b1) -> fp16 h1 rows ----------------
__global__ __launch_bounds__(256) void lin1_kernel(
    const float* __restrict__ xin, const float* __restrict__ Wl,
    const float* __restrict__ bl, const float* __restrict__ Wr)
{
    __shared__ __align__(16) float sAT[KDIM][36];
    __shared__ float sW[KDIM * F1];
    __shared__ float sbl[F1];

    const int tid = threadIdx.x;
    const int jt = tid & 31;
    const int mt = tid >> 5;
    const int base_n = blockIdx.x * 32;

    for (int idx = tid; idx < KDIM * F1; idx += 256) {
        int k = idx / F1, j = idx - k * F1;
        sW[idx] = (k < F1) ? Wl[k * F1 + j] : Wr[(k - F1) * F1 + j];
    }
    if (tid < F1) sbl[tid] = bl[tid];
    for (int idx = tid; idx < 32 * F1; idx += 256) {
        int m = idx & 31, k = idx >> 5;
        long n = base_n + m;
        sAT[k][m]      = __half2float(d_a2[n * APAD + k]);
        sAT[k + F1][m] = xin[n * F1 + k];
    }
    __syncthreads();

    unsigned long long acc2[2][2];
#pragma unroll
    for (int p = 0; p < 2; p++)
#pragma unroll
        for (int c = 0; c < 2; c++) acc2[p][c] = 0ULL;

#pragma unroll 2
    for (int k = 0; k < KDIM; k++) {
        float4 a4 = *(const float4*)&sAT[k][mt * 4];
        unsigned long long a01, a23;
        PACK_F32X2(a01, a4.x, a4.y);
        PACK_F32X2(a23, a4.z, a4.w);
#pragma unroll
        for (int c = 0; c < 2; c++) {
            int j = jt + 32 * c;
            float w = (j < F1) ? sW[k * F1 + j] : 0.f;
            unsigned long long ww;
            PACK_F32X2(ww, w, w);
            FMA_F32X2(acc2[0][c], a01, ww, acc2[0][c]);
            FMA_F32X2(acc2[1][c], a23, ww, acc2[1][c]);
        }
    }

    const int n0 = base_n + mt * 4;
    float v[4];
#pragma unroll
    for (int c = 0; c < 2; c++) {
        int j = jt + 32 * c;
        if (j < F1) {
            UNPACK_F32X2(v[0], v[1], acc2[0][c]);
            UNPACK_F32X2(v[2], v[3], acc2[1][c]);
#pragma unroll
            for (int r = 0; r < 4; r++) {
                float o = fmaxf(v[r] + sbl[j], 0.f);
                d_xh[(long)(n0 + r) * RPAD + j] = __float2half(o);
            }
        }
    }
}

// ---------------- K6: lin2 + max-pool: HMMA m16n8k16, 64 nodes/block ----------------
__global__ __launch_bounds__(256) void mma_pool_kernel(
    const float* __restrict__ Wl, const float* __restrict__ bl,
    const float* __restrict__ Wr, const int* __restrict__ batch)
{
    __shared__ __align__(16) __half sA[64 * 88];
    __shared__ __align__(16) __half sB[128 * 88];
    __shared__ float sbl[F2];
    __shared__ int   sgm[F2];

    const int tid = threadIdx.x;
    const int w = tid >> 5;
    const int lane = tid & 31;
    const int gid = lane >> 2;
    const int tig = lane & 3;
    const int base = blockIdx.x * 64;

    for (int idx = tid; idx < 64 * 80; idx += 256) {
        int m = idx / 80, k = idx - (idx / 80) * 80;
        long n = base + m;
        __half v = __ushort_as_half((unsigned short)0);
        if (n < N_NODES) {
            if (k < F1) v = d_a2[n * APAD + k];
            else if (k < KDIM) v = d_xh[n * RPAD + (k - F1)];
        }
        sA[m * 88 + k] = v;
    }
    for (int idx = tid; idx < 80 * F2; idx += 256) {
        int k = idx >> 7, n = idx & 127;
        float v = 0.f;
        if (k < F1) v = Wl[k * F2 + n];
        else if (k < KDIM) v = Wr[(k - F1) * F2 + n];
        sB[n * 88 + k] = __float2half(v);
    }
    if (tid < F2) { sbl[tid] = bl[tid]; sgm[tid] = (int)0x80000000; }
    __syncthreads();

    const int wm = w & 3;
    const int wn = (w >> 2) * 8;
    float acc[8][4];
#pragma unroll
    for (int nt = 0; nt < 8; nt++)
#pragma unroll
        for (int c = 0; c < 4; c++) acc[nt][c] = 0.f;

#pragma unroll
    for (int kc = 0; kc < 5; kc++) {
        const int k0 = kc * 16;
        unsigned a[4];
        const int ra = (wm * 16 + gid) * 88 + k0 + tig * 2;
        a[0] = *(const unsigned*)&sA[ra];
        a[1] = *(const unsigned*)&sA[ra + 8 * 88];
        a[2] = *(const unsigned*)&sA[ra + 8];
        a[3] = *(const unsigned*)&sA[ra + 8 * 88 + 8];
#pragma unroll
        for (int nt = 0; nt < 8; nt++) {
            unsigned b[2];
            const int rb = ((wn + nt) * 8 + gid) * 88 + k0 + tig * 2;
            b[0] = *(const unsigned*)&sB[rb];
            b[1] = *(const unsigned*)&sB[rb + 8];
            mma16816(acc[nt], a, b);
        }
    }

    const int r0 = base + wm * 16 + gid;
    const int r1 = r0 + 8;
    const bool full = (base + 63 < N_NODES);
    const int gfirst = batch[base];
    const bool single = full && (gfirst == batch[base + 63]);

    if (single) {
#pragma unroll
        for (int nt = 0; nt < 8; nt++) {
            int c0 = (wn + nt) * 8 + tig * 2;
            int k0v = max(fkey(acc[nt][0] + sbl[c0]),     fkey(acc[nt][2] + sbl[c0]));
            int k1v = max(fkey(acc[nt][1] + sbl[c0 + 1]), fkey(acc[nt][3] + sbl[c0 + 1]));
            atomicMax(&sgm[c0], k0v);
            atomicMax(&sgm[c0 + 1], k1v);
        }
        __syncthreads();
        if (tid < F2) atomicMax(&d_gmax[gfirst * F2 + tid], sgm[tid]);
    } else {
        int b0 = (r0 < N_NODES) ? batch[r0] : -1;
        int b1 = (r1 < N_NODES) ? batch[r1] : -1;
#pragma unroll
        for (int nt = 0; nt < 8; nt++) {
            int c0 = (wn + nt) * 8 + tig * 2;
            if (b0 >= 0) {
                atomicMax(&d_gmax[b0 * F2 + c0],     fkey(acc[nt][0] + sbl[c0]));
                atomicMax(&d_gmax[b0 * F2 + c0 + 1], fkey(acc[nt][1] + sbl[c0 + 1]));
            }
            if (b1 >= 0) {
                atomicMax(&d_gmax[b1 * F2 + c0],     fkey(acc[nt][2] + sbl[c0]));
                atomicMax(&d_gmax[b1 * F2 + c0 + 1], fkey(acc[nt][3] + sbl[c0 + 1]));
            }
        }
    }
}

// ---------------- K7: FC head ----------------
__global__ __launch_bounds__(128) void head_kernel(
    const float* __restrict__ Wg1, const float* __restrict__ bg1,
    const float* __restrict__ Wg2, const float* __restrict__ bg2,
    const float* __restrict__ Wo,  const float* __restrict__ bo,
    float* __restrict__ out)
{
    int g = blockIdx.x, j = threadIdx.x;
    __shared__ float r0[F2], r1[F2];
    __shared__ float wred[4];
    int key = d_gmax[g * F2 + j];
    key = key >= 0 ? key : (key ^ 0x7FFFFFFF);
    r0[j] = __int_as_float(key);
    __syncthreads();
    float acc = bg1[j];
#pragma unroll 8
    for (int k = 0; k < F2; k++) acc += r0[k] * Wg1[k * F2 + j];
    r1[j] = fmaxf(acc, 0.f);
    __syncthreads();
    acc = bg2[j];
#pragma unroll 8
    for (int k = 0; k < F2; k++) acc += r1[k] * Wg2[k * F2 + j];
    float v = fmaxf(acc, 0.f) * Wo[j];
#pragma unroll
    for (int s = 16; s > 0; s >>= 1) v += __shfl_down_sync(0xffffffffu, v, s);
    if ((j & 31) == 0) wred[j >> 5] = v;
    __syncthreads();
    if (j == 0) out[g] = wred[0] + wred[1] + wred[2] + wred[3] + bo[0];
}

// ---------------- launcher (8 kernels; agg1 at capture index 3) ----------------
extern "C" void kernel_launch(void* const* d_in, const int* in_sizes, int n_in,
                              void* d_out, int out_size) {
    const float* x    = (const float*)d_in[0];
    const int*   ei   = (const int*)d_in[1];
    const int*   bat  = (const int*)d_in[2];
    const float* Wl1  = (const float*)d_in[3];
    const float* bl1  = (const float*)d_in[4];
    const float* Wr1  = (const float*)d_in[5];
    const float* Wl2  = (const float*)d_in[6];
    const float* bl2  = (const float*)d_in[7];
    const float* Wr2  = (const float*)d_in[8];
    const float* Wg1  = (const float*)d_in[9];
    const float* bg1  = (const float*)d_in[10];
    const float* Wg2  = (const float*)d_in[11];
    const float* bg2  = (const float*)d_in[12];
    const float* Wo   = (const float*)d_in[13];
    const float* bo   = (const float*)d_in[14];
    float* out = (float*)d_out;

    const int* src = ei;
    const int* dst = ei + N_EDGES;

    pre_kernel<<<CNT_BLK + CONV_BLK, 256>>>(x, dst);                    // 0
    scan_kernel<<<NB, 1024>>>();                                        // 1
    fill_kernel<<<(N_EDGES / 4 + 255) / 256, 256>>>(src, dst);          // 2

    agg_kernel<<<(N_NODES * 32 + 255) / 256, 256>>>();                  // 3 <- profiled
    lin1_kernel<<<N_NODES / 32, 256>>>(x, Wl1, bl1, Wr1);               // 4

    agg_kernel<<<(N_NODES * 32 + 255) / 256, 256>>>();                  // 5
    mma_pool_kernel<<<(N_NODES + 63) / 64, 256>>>(Wl2, bl2, Wr2, bat);  // 6

    head_kernel<<<N_GRAPHS, F2>>>(Wg1, bg1, Wg2, bg2, Wo, bo, out);     // 7
}